// round 6
// baseline (speedup 1.0000x reference)
#include <cuda_runtime.h>
#include <cuda_bf16.h>
#include <cstdint>

// Problem constants
#define B_SZ 8
#define T_SEQ 2048
#define D_MODEL 768
#define D_STATE 16
#define D_CONV 4
#define M_ROWS (B_SZ * T_SEQ)          // 16384
#define NCH 16                          // scan chunks
#define TCH (T_SEQ / NCH)               // 128 steps per chunk
#define NCAT 896                        // padded fused-GEMM2 N (768 dt + 16 B + 16 C + 96 pad)

// ---------------- scratch (__device__ globals; no runtime alloc) -------------
__device__ __nv_bfloat16 g_xbf     [M_ROWS * D_MODEL];
__device__ __nv_bfloat16 g_xssm_bf [M_ROWS * D_MODEL];
__device__ __nv_bfloat16 g_xconv_bf[M_ROWS * D_MODEL];
__device__ __nv_bfloat16 g_Win_bf  [D_MODEL * D_MODEL];
__device__ __nv_bfloat16 g_Wcat_bf [NCAT * D_MODEL];
__device__ float g_dt   [M_ROWS * D_MODEL];
__device__ float g_Bm   [M_ROWS * D_STATE];
__device__ float g_Cm   [M_ROWS * D_STATE];
__device__ float g_hend [B_SZ * NCH * D_STATE * D_MODEL];
__device__ float g_Pp   [B_SZ * NCH * D_STATE * D_MODEL];
__device__ float g_sin  [B_SZ * NCH * D_STATE * D_MODEL];

// ============================ PTX helpers =====================================
__device__ __forceinline__ uint32_t smem_u32(const void* p) {
    uint32_t a;
    asm("{ .reg .u64 t; cvta.to.shared.u64 t, %1; cvt.u32.u64 %0, t; }" : "=r"(a) : "l"(p));
    return a;
}
__device__ __forceinline__ void ldsm_x4(uint32_t addr, uint32_t& r0, uint32_t& r1,
                                        uint32_t& r2, uint32_t& r3) {
    asm volatile("ldmatrix.sync.aligned.m8n8.x4.shared.b16 {%0,%1,%2,%3}, [%4];"
                 : "=r"(r0), "=r"(r1), "=r"(r2), "=r"(r3) : "r"(addr));
}
__device__ __forceinline__ void mma_bf16(float* c,
                                         uint32_t a0, uint32_t a1, uint32_t a2, uint32_t a3,
                                         uint32_t b0, uint32_t b1) {
    asm volatile("mma.sync.aligned.m16n8k16.row.col.f32.bf16.bf16.f32 "
                 "{%0,%1,%2,%3}, {%4,%5,%6,%7}, {%8,%9}, {%0,%1,%2,%3};"
                 : "+f"(c[0]), "+f"(c[1]), "+f"(c[2]), "+f"(c[3])
                 : "r"(a0), "r"(a1), "r"(a2), "r"(a3), "r"(b0), "r"(b1));
}
__device__ __forceinline__ __nv_bfloat16 f2bf(float x) { return __float2bfloat16_rn(x); }

#define CP16(dst, src) \
    asm volatile("cp.async.cg.shared.global [%0], [%1], 16;" :: "r"(dst), "l"(src) : "memory")
#define CP_COMMIT()  asm volatile("cp.async.commit_group;" ::: "memory")
#define CP_WAIT2()   asm volatile("cp.async.wait_group 2;" ::: "memory")

// ---- packed f32x2 (Blackwell family-wide: sm_100+) ----
__device__ __forceinline__ uint64_t pack2(float lo, float hi) {
    uint64_t r; asm("mov.b64 %0, {%1,%2};" : "=l"(r) : "f"(lo), "f"(hi)); return r;
}
__device__ __forceinline__ void unpack2(uint64_t v, float& lo, float& hi) {
    asm("mov.b64 {%0,%1}, %2;" : "=f"(lo), "=f"(hi) : "l"(v));
}
__device__ __forceinline__ uint64_t mul2(uint64_t a, uint64_t b) {
    uint64_t r; asm("mul.rn.f32x2 %0, %1, %2;" : "=l"(r) : "l"(a), "l"(b)); return r;
}
__device__ __forceinline__ uint64_t fma2(uint64_t a, uint64_t b, uint64_t c) {
    uint64_t r; asm("fma.rn.f32x2 %0, %1, %2, %3;" : "=l"(r) : "l"(a), "l"(b), "l"(c)); return r;
}
__device__ __forceinline__ uint64_t lds64(uint32_t addr) {
    uint64_t r; asm volatile("ld.shared.b64 %0, [%1];" : "=l"(r) : "r"(addr)); return r;
}

// ===================== bf16 mma.sync GEMM =====================================
// C[M, N] = A[M, 768](bf16) * W[N, 768](bf16)^T, fp32 accumulate.
// tile 128x128, BK=32, 4-stage cp.async pipeline (dynamic smem). 8 warps, 64x32 each.
// mode 0: write bf16 to outBF (no act).
// mode 1: fused epilogue: cols <768 -> softplus(v + bias) into outDT (fp32);
//         cols 768..783 -> Bm; 784..799 -> Cm; >=800 discard.
#define GK 768
#define CHKB 32
#define NKB (GK / CHKB)                 // 24
#define SRB 40                          // 32 + 8 pad bf16 (80B row; LDSM conflict-free)
#define ROWB (SRB * 2)                  // 80 bytes per smem row
#define MATB (128 * ROWB)               // 10240 bytes per matrix per stage
#define STGB (2 * MATB)                 // 20480 bytes per stage (A + W)
#define NSTG 4
#define GEMM_SMEM (NSTG * STGB)         // 81920

__global__ __launch_bounds__(256, 2)
void gemm_bf16(const __nv_bfloat16* __restrict__ A, const __nv_bfloat16* __restrict__ W,
               const float* __restrict__ bias, __nv_bfloat16* __restrict__ outBF,
               float* __restrict__ outDT, float* __restrict__ Bm, float* __restrict__ Cm,
               int mode)
{
    extern __shared__ __align__(16) char smem_raw[];
    const uint32_t sbase = smem_u32(smem_raw);

    const int tid  = threadIdx.x;
    const int wid  = tid >> 5;
    const int lane = tid & 31;
    const int bn   = blockIdx.x * 128;
    const int bm   = blockIdx.y * 128;
    const int wm   = (wid & 1) * 64;
    const int wn   = (wid >> 1) * 32;

    float acc[4][4][4];
    #pragma unroll
    for (int i = 0; i < 4; i++)
        #pragma unroll
        for (int j = 0; j < 4; j++)
            #pragma unroll
            for (int c = 0; c < 4; c++) acc[i][j][c] = 0.f;

    // cp.async pattern: per chunk per matrix 128 rows x 64B = 512 x 16B; 2/thread/matrix
    const int r0 = tid >> 2;              // 0..63
    const int c8 = (tid & 3) * 8;         // bf16 elem offset 0,8,16,24
    const __nv_bfloat16* Aptr = A + (size_t)(bm + r0) * GK + c8;
    const __nv_bfloat16* Wptr = W + (size_t)(bn + r0) * GK + c8;
    const size_t gstep = (size_t)64 * GK;

    const uint32_t dA0 = sbase + (uint32_t)(r0 * ROWB + c8 * 2);
    const uint32_t dW0 = dA0 + MATB;

    auto issue = [&](int k) {
        uint32_t off = (uint32_t)(k % NSTG) * STGB;
        const __nv_bfloat16* a0 = Aptr + (size_t)k * CHKB;
        const __nv_bfloat16* w0 = Wptr + (size_t)k * CHKB;
        CP16(dA0 + off,                 a0);
        CP16(dA0 + off + 64u * ROWB,    a0 + gstep);
        CP16(dW0 + off,                 w0);
        CP16(dW0 + off + 64u * ROWB,    w0 + gstep);
        CP_COMMIT();
    };

    // ldmatrix lane addressing (validated round 4)
    const int arow = lane & 15;                       // A: rows m0..15
    const int ak   = (lane >> 4) * 8;                 // A: k half
    const int brow = ((lane >> 4) * 8) + (lane & 7);  // B: n row within 16
    const int bk   = ((lane >> 3) & 1) * 8;           // B: k half

    const uint32_t aAddr0 = sbase + (uint32_t)((wm + arow) * ROWB + ak * 2);
    const uint32_t bAddr0 = sbase + MATB + (uint32_t)((wn + brow) * ROWB + bk * 2);

    issue(0);
    issue(1);
    issue(2);

    for (int k = 0; k < NKB; k++) {
        CP_WAIT2();
        __syncthreads();
        if (k + 3 < NKB) issue(k + 3);

        const uint32_t off = (uint32_t)(k % NSTG) * STGB;
        #pragma unroll
        for (int ks = 0; ks < 2; ks++) {
            const uint32_t koff = off + (uint32_t)(ks * 32);   // 16 bf16 = 32 bytes
            uint32_t bf[4][2];
            ldsm_x4(bAddr0 + koff,               bf[0][0], bf[0][1], bf[1][0], bf[1][1]);
            ldsm_x4(bAddr0 + koff + 16u * ROWB,  bf[2][0], bf[2][1], bf[3][0], bf[3][1]);
            #pragma unroll
            for (int mf = 0; mf < 4; mf++) {
                uint32_t a0, a1, a2, a3;
                ldsm_x4(aAddr0 + koff + (uint32_t)(mf * 16 * ROWB), a0, a1, a2, a3);
                #pragma unroll
                for (int nf = 0; nf < 4; nf++)
                    mma_bf16(acc[mf][nf], a0, a1, a2, a3, bf[nf][0], bf[nf][1]);
            }
        }
    }

    // epilogue: c0/c1 = (row, col/col+1); c2/c3 = row+8
    const int erow = lane >> 2;
    const int ecol = (lane & 3) * 2;
    #pragma unroll
    for (int mf = 0; mf < 4; mf++) {
        int row = bm + wm + mf * 16 + erow;
        #pragma unroll
        for (int nf = 0; nf < 4; nf++) {
            int col = bn + wn + nf * 8 + ecol;
            float v0 = acc[mf][nf][0], v1 = acc[mf][nf][1];
            float v2 = acc[mf][nf][2], v3 = acc[mf][nf][3];
            if (mode == 0) {
                __nv_bfloat162 p0 = { f2bf(v0), f2bf(v1) };
                __nv_bfloat162 p1 = { f2bf(v2), f2bf(v3) };
                *reinterpret_cast<__nv_bfloat162*>(outBF + (size_t)row * D_MODEL + col)       = p0;
                *reinterpret_cast<__nv_bfloat162*>(outBF + (size_t)(row + 8) * D_MODEL + col) = p1;
            } else if (col < 768) {
                float b0 = bias[col], b1 = bias[col + 1];
                v0 += b0; v1 += b1; v2 += b0; v3 += b1;
                v0 = (v0 > 20.f) ? v0 : log1pf(__expf(v0));
                v1 = (v1 > 20.f) ? v1 : log1pf(__expf(v1));
                v2 = (v2 > 20.f) ? v2 : log1pf(__expf(v2));
                v3 = (v3 > 20.f) ? v3 : log1pf(__expf(v3));
                *reinterpret_cast<float2*>(outDT + (size_t)row * D_MODEL + col)       = make_float2(v0, v1);
                *reinterpret_cast<float2*>(outDT + (size_t)(row + 8) * D_MODEL + col) = make_float2(v2, v3);
            } else if (col < 784) {
                int n = col - 768;
                *reinterpret_cast<float2*>(Bm + (size_t)row * D_STATE + n)       = make_float2(v0, v1);
                *reinterpret_cast<float2*>(Bm + (size_t)(row + 8) * D_STATE + n) = make_float2(v2, v3);
            } else if (col < 800) {
                int n = col - 784;
                *reinterpret_cast<float2*>(Cm + (size_t)row * D_STATE + n)       = make_float2(v0, v1);
                *reinterpret_cast<float2*>(Cm + (size_t)(row + 8) * D_STATE + n) = make_float2(v2, v3);
            }
        }
    }
}

// ---------------- fp32 -> bf16 bulk convert ----------------------------------
__global__ void cvt_f32_bf16(const float* __restrict__ in, __nv_bfloat16* __restrict__ out, int n4)
{
    int idx = blockIdx.x * blockDim.x + threadIdx.x;
    if (idx >= n4) return;
    float4 v = reinterpret_cast<const float4*>(in)[idx];
    __nv_bfloat162 lo = { f2bf(v.x), f2bf(v.y) };
    __nv_bfloat162 hi = { f2bf(v.z), f2bf(v.w) };
    uint2 u = { *reinterpret_cast<uint32_t*>(&lo), *reinterpret_cast<uint32_t*>(&hi) };
    reinterpret_cast<uint2*>(out)[idx] = u;
}

// ---------------- build concatenated weight (bf16) ---------------------------
__global__ void build_wcat(const float* __restrict__ W_dt, const float* __restrict__ W_B,
                           const float* __restrict__ W_C, __nv_bfloat16* __restrict__ out)
{
    int idx = blockIdx.x * blockDim.x + threadIdx.x;
    if (idx >= NCAT * D_MODEL / 4) return;
    int r  = idx / (D_MODEL / 4);
    int c4 = (idx % (D_MODEL / 4)) * 4;
    float4 v = make_float4(0.f, 0.f, 0.f, 0.f);
    if (r < 768)      v = *reinterpret_cast<const float4*>(W_dt + (size_t)r * D_MODEL + c4);
    else if (r < 784) v = *reinterpret_cast<const float4*>(W_B + (size_t)(r - 768) * D_MODEL + c4);
    else if (r < 800) v = *reinterpret_cast<const float4*>(W_C + (size_t)(r - 784) * D_MODEL + c4);
    __nv_bfloat162 lo = { f2bf(v.x), f2bf(v.y) };
    __nv_bfloat162 hi = { f2bf(v.z), f2bf(v.w) };
    uint2 u = { *reinterpret_cast<uint32_t*>(&lo), *reinterpret_cast<uint32_t*>(&hi) };
    reinterpret_cast<uint2*>(out)[idx] = u;
}

// ---------------- depthwise causal conv (K=4) + bias + SiLU, 4-wide ----------
__global__ void conv_silu_bf16(const __nv_bfloat16* __restrict__ xin,
                               const float* __restrict__ cw,
                               const float* __restrict__ cb,
                               __nv_bfloat16* __restrict__ out)
{
    int idx = blockIdx.x * blockDim.x + threadIdx.x;   // quad index
    if (idx >= M_ROWS * D_MODEL / 4) return;
    int q  = idx % (D_MODEL / 4);
    int t  = (idx / (D_MODEL / 4)) % T_SEQ;
    int d  = q * 4;

    float a[4] = { cb[d], cb[d + 1], cb[d + 2], cb[d + 3] };
    #pragma unroll
    for (int k = 0; k < D_CONV; k++) {
        int rel = k - (D_CONV - 1);
        if (t + rel >= 0) {
            uint2 raw = reinterpret_cast<const uint2*>(xin)[idx + rel * (D_MODEL / 4)];
            __nv_bfloat162 p0 = *reinterpret_cast<__nv_bfloat162*>(&raw.x);
            __nv_bfloat162 p1 = *reinterpret_cast<__nv_bfloat162*>(&raw.y);
            a[0] = fmaf(__bfloat162float(p0.x), cw[(d + 0) * D_CONV + k], a[0]);
            a[1] = fmaf(__bfloat162float(p0.y), cw[(d + 1) * D_CONV + k], a[1]);
            a[2] = fmaf(__bfloat162float(p1.x), cw[(d + 2) * D_CONV + k], a[2]);
            a[3] = fmaf(__bfloat162float(p1.y), cw[(d + 3) * D_CONV + k], a[3]);
        }
    }
    __nv_bfloat162 o0 = { f2bf(a[0] / (1.f + __expf(-a[0]))), f2bf(a[1] / (1.f + __expf(-a[1]))) };
    __nv_bfloat162 o1 = { f2bf(a[2] / (1.f + __expf(-a[2]))), f2bf(a[3] / (1.f + __expf(-a[3]))) };
    uint2 o = { *reinterpret_cast<uint32_t*>(&o0), *reinterpret_cast<uint32_t*>(&o1) };
    reinterpret_cast<uint2*>(out)[idx] = o;
}

// ---------------- scan helpers ------------------------------------------------
__device__ __forceinline__ void load_A_and_mode(const float* __restrict__ A_log,
                                                int d, float* A, bool& fast)
{
    #pragma unroll
    for (int n = 0; n < D_STATE; n++) A[n] = -__expf(A_log[d * D_STATE + n]);
    fast = true;
    #pragma unroll
    for (int n = 1; n < D_STATE; n++)
        fast = fast && (fabsf(A[n] - (float)(n + 1) * A[0]) <= 1e-4f * fabsf(A[n]));
}

// packed powers: pw2[k] = (p^(2k+1), p^(2k+2))
__device__ __forceinline__ void powers16_p2(float p, uint64_t* pw2)
{
    float p2 = p * p;
    uint64_t st = pack2(p2, p2);
    pw2[0] = pack2(p, p2);
    #pragma unroll
    for (int k = 1; k < 8; k++) pw2[k] = mul2(pw2[k - 1], st);
}

// scalar powers (epilogue use): pw[n] = p^(n+1)
__device__ __forceinline__ void powers16(float p1, float* pw)
{
    float p2 = p1 * p1, p4 = p2 * p2, p8 = p4 * p4;
    pw[0] = p1;        pw[1] = p2;        pw[2] = p2 * p1;   pw[3] = p4;
    pw[4] = p4 * p1;   pw[5] = p4 * p2;   pw[6] = p4 * pw[2]; pw[7] = p8;
    pw[8] = p8 * p1;   pw[9] = p8 * p2;   pw[10] = p8 * pw[2]; pw[11] = p8 * p4;
    pw[12] = p8 * pw[4]; pw[13] = p8 * pw[5]; pw[14] = p8 * pw[6]; pw[15] = p8 * p8;
}

// pass 1: per-chunk local scan from h=0; emit end-state and cumulative decay
__global__ __launch_bounds__(256)
void scan_pass1(const float* __restrict__ dt, const float* __restrict__ Bm,
                const float* __restrict__ x,  const float* __restrict__ A_log,
                float* __restrict__ hend, float* __restrict__ Pp)
{
    __shared__ float sB[TCH * D_STATE];
    int d  = blockIdx.x * blockDim.x + threadIdx.x;
    int ch = blockIdx.y;
    int b  = blockIdx.z;
    int t0 = ch * TCH;

    {
        const float4* src = reinterpret_cast<const float4*>(Bm + ((size_t)(b * T_SEQ + t0)) * D_STATE);
        float4* dst = reinterpret_cast<float4*>(sB);
        for (int i = threadIdx.x; i < TCH * D_STATE / 4; i += blockDim.x) dst[i] = src[i];
    }
    __syncthreads();

    float A[D_STATE]; bool fast;
    load_A_and_mode(A_log, d, A, fast);

    const float* dtp = dt + ((size_t)(b * T_SEQ + t0)) * D_MODEL + d;
    const float* xp  = x  + ((size_t)(b * T_SEQ + t0)) * D_MODEL + d;
    size_t base = ((size_t)(b * NCH + ch) * D_STATE) * D_MODEL + d;
    const uint32_t sBaddr = smem_u32(sB);

    if (fast) {
        const float A0 = A[0];
        uint64_t h2[8];
        #pragma unroll
        for (int k = 0; k < 8; k++) h2[k] = 0ull;
        float S = 0.f;
        for (int t = 0; t < TCH; t += 4) {
            float dtv[4], xv[4];
            #pragma unroll
            for (int j = 0; j < 4; j++) {
                dtv[j] = dtp[(size_t)(t + j) * D_MODEL];
                xv[j]  = xp [(size_t)(t + j) * D_MODEL];
            }
            #pragma unroll
            for (int j = 0; j < 4; j++) {
                float u = xv[j] * dtv[j];
                S += dtv[j];
                uint64_t pw2[8];
                powers16_p2(__expf(A0 * dtv[j]), pw2);
                uint64_t u2 = pack2(u, u);
                uint32_t ba = sBaddr + (uint32_t)((t + j) * 64);
                #pragma unroll
                for (int k = 0; k < 8; k++) {
                    uint64_t b2 = lds64(ba + k * 8);
                    h2[k] = fma2(h2[k], pw2[k], mul2(u2, b2));
                }
            }
        }
        float pw[16];
        powers16(__expf(A0 * S), pw);
        #pragma unroll
        for (int k = 0; k < 8; k++) {
            float hlo, hhi;
            unpack2(h2[k], hlo, hhi);
            hend[base + (size_t)(2 * k)     * D_MODEL] = hlo;
            hend[base + (size_t)(2 * k + 1) * D_MODEL] = hhi;
            Pp  [base + (size_t)(2 * k)     * D_MODEL] = pw[2 * k];
            Pp  [base + (size_t)(2 * k + 1) * D_MODEL] = pw[2 * k + 1];
        }
    } else {
        float h[D_STATE], P[D_STATE];
        #pragma unroll
        for (int n = 0; n < D_STATE; n++) { h[n] = 0.f; P[n] = 1.f; }
        for (int t = 0; t < TCH; t++) {
            float dtv = dtp[(size_t)t * D_MODEL];
            float xv  = xp [(size_t)t * D_MODEL];
            float u   = xv * dtv;
            const float* Bt = sB + t * D_STATE;
            #pragma unroll
            for (int n = 0; n < D_STATE; n++) {
                float pw = __expf(A[n] * dtv);
                h[n] = fmaf(h[n], pw, u * Bt[n]);
                P[n] *= pw;
            }
        }
        #pragma unroll
        for (int n = 0; n < D_STATE; n++) {
            hend[base + (size_t)n * D_MODEL] = h[n];
            Pp  [base + (size_t)n * D_MODEL] = P[n];
        }
    }
}

// pass 2: sequential combine over chunks -> chunk-entry states
__global__ void scan_combine(const float* __restrict__ hend, const float* __restrict__ Pp,
                             float* __restrict__ sin_)
{
    int idx = blockIdx.x * blockDim.x + threadIdx.x;
    if (idx >= B_SZ * D_STATE * D_MODEL) return;
    int d = idx % D_MODEL;
    int n = (idx / D_MODEL) % D_STATE;
    int b = idx / (D_MODEL * D_STATE);

    float s = 0.f;
    for (int ch = 0; ch < NCH; ch++) {
        size_t off = ((size_t)(b * NCH + ch) * D_STATE + n) * D_MODEL + d;
        sin_[off] = s;
        s = fmaf(Pp[off], s, hend[off]);
    }
}

// pass 3: replay chunks with correct entry state; emit y + residual
__global__ __launch_bounds__(256)
void scan_pass3(const float* __restrict__ dt, const float* __restrict__ Bm,
                const float* __restrict__ Cm, const float* __restrict__ x,
                const float* __restrict__ A_log, const float* __restrict__ Dp,
                const float* __restrict__ sin_, float* __restrict__ y)
{
    __shared__ float sB[TCH * D_STATE];
    __shared__ float sC[TCH * D_STATE];
    int d  = blockIdx.x * blockDim.x + threadIdx.x;
    int ch = blockIdx.y;
    int b  = blockIdx.z;
    int t0 = ch * TCH;

    {
        const float4* srcB = reinterpret_cast<const float4*>(Bm + ((size_t)(b * T_SEQ + t0)) * D_STATE);
        const float4* srcC = reinterpret_cast<const float4*>(Cm + ((size_t)(b * T_SEQ + t0)) * D_STATE);
        float4* dB = reinterpret_cast<float4*>(sB);
        float4* dC = reinterpret_cast<float4*>(sC);
        for (int i = threadIdx.x; i < TCH * D_STATE / 4; i += blockDim.x) { dB[i] = srcB[i]; dC[i] = srcC[i]; }
    }
    __syncthreads();

    float A[D_STATE]; bool fast;
    load_A_and_mode(A_log, d, A, fast);

    size_t base = ((size_t)(b * NCH + ch) * D_STATE) * D_MODEL + d;
    float dpar = Dp[d];
    const float* dtp = dt + ((size_t)(b * T_SEQ + t0)) * D_MODEL + d;
    const float* xp  = x  + ((size_t)(b * T_SEQ + t0)) * D_MODEL + d;
    float* yp        = y  + ((size_t)(b * T_SEQ + t0)) * D_MODEL + d;
    const uint32_t sBaddr = smem_u32(sB);
    const uint32_t sCaddr = smem_u32(sC);

    if (fast) {
        const float A0 = A[0];
        uint64_t h2[8];
        #pragma unroll
        for (int k = 0; k < 8; k++)
            h2[k] = pack2(sin_[base + (size_t)(2 * k) * D_MODEL],
                          sin_[base + (size_t)(2 * k + 1) * D_MODEL]);

        for (int t = 0; t < TCH; t += 4) {
            float dtv[4], xv[4];
            #pragma unroll
            for (int j = 0; j < 4; j++) {
                dtv[j] = dtp[(size_t)(t + j) * D_MODEL];
                xv[j]  = xp [(size_t)(t + j) * D_MODEL];
            }
            float yv[4];
            #pragma unroll
            for (int j = 0; j < 4; j++) {
                float u = xv[j] * dtv[j];
                uint64_t pw2[8];
                powers16_p2(__expf(A0 * dtv[j]), pw2);
                uint64_t u2 = pack2(u, u);
                uint32_t ba = sBaddr + (uint32_t)((t + j) * 64);
                uint32_t ca = sCaddr + (uint32_t)((t + j) * 64);
                uint64_t acc2 = 0ull;
                #pragma unroll
                for (int k = 0; k < 8; k++) {
                    uint64_t b2 = lds64(ba + k * 8);
                    uint64_t c2 = lds64(ca + k * 8);
                    h2[k] = fma2(h2[k], pw2[k], mul2(u2, b2));
                    acc2  = fma2(h2[k], c2, acc2);
                }
                float alo, ahi;
                unpack2(acc2, alo, ahi);
                yv[j] = fmaf(xv[j], dpar, alo + ahi);
            }
            #pragma unroll
            for (int j = 0; j < 4; j++)
                yp[(size_t)(t + j) * D_MODEL] = yv[j];
        }
    } else {
        float h[D_STATE];
        #pragma unroll
        for (int n = 0; n < D_STATE; n++) h[n] = sin_[base + (size_t)n * D_MODEL];
        for (int t = 0; t < TCH; t++) {
            float dtv = dtp[(size_t)t * D_MODEL];
            float xv  = xp [(size_t)t * D_MODEL];
            float u   = xv * dtv;
            const float* Bt = sB + t * D_STATE;
            const float* Ct = sC + t * D_STATE;
            float acc = 0.f;
            #pragma unroll
            for (int n = 0; n < D_STATE; n++) {
                float pw = __expf(A[n] * dtv);
                h[n] = fmaf(h[n], pw, u * Bt[n]);
                acc  = fmaf(h[n], Ct[n], acc);
            }
            yp[(size_t)t * D_MODEL] = fmaf(xv, dpar, acc);
        }
    }
}

// ---------------- launch ------------------------------------------------------
extern "C" void kernel_launch(void* const* d_in, const int* in_sizes, int n_in,
                              void* d_out, int out_size)
{
    const float* x      = (const float*)d_in[0];
    const float* W_in   = (const float*)d_in[1];
    const float* conv_w = (const float*)d_in[2];
    const float* conv_b = (const float*)d_in[3];
    const float* W_dt   = (const float*)d_in[4];
    const float* b_dt   = (const float*)d_in[5];
    const float* A_log  = (const float*)d_in[6];
    const float* D_par  = (const float*)d_in[7];
    const float* W_B    = (const float*)d_in[8];
    const float* W_C    = (const float*)d_in[9];
    float* y = (float*)d_out;

    __nv_bfloat16 *xbf, *xssm_bf, *xconv_bf, *win_bf, *wcat_bf;
    float *dtb, *Bm, *Cm, *hend, *Pp, *sin_;
    cudaGetSymbolAddress((void**)&xbf,      g_xbf);
    cudaGetSymbolAddress((void**)&xssm_bf,  g_xssm_bf);
    cudaGetSymbolAddress((void**)&xconv_bf, g_xconv_bf);
    cudaGetSymbolAddress((void**)&win_bf,   g_Win_bf);
    cudaGetSymbolAddress((void**)&wcat_bf,  g_Wcat_bf);
    cudaGetSymbolAddress((void**)&dtb,   g_dt);
    cudaGetSymbolAddress((void**)&Bm,    g_Bm);
    cudaGetSymbolAddress((void**)&Cm,    g_Cm);
    cudaGetSymbolAddress((void**)&hend,  g_hend);
    cudaGetSymbolAddress((void**)&Pp,    g_Pp);
    cudaGetSymbolAddress((void**)&sin_,  g_sin);

    cudaFuncSetAttribute(gemm_bf16, cudaFuncAttributeMaxDynamicSharedMemorySize, GEMM_SMEM);

    // 0) precision prep: x -> bf16; W_in[:768] -> bf16; [W_dt; W_B; W_C; 0] -> bf16
    int n4x = M_ROWS * D_MODEL / 4;
    cvt_f32_bf16<<<(n4x + 255) / 256, 256>>>(x, xbf, n4x);
    int n4w = D_MODEL * D_MODEL / 4;
    cvt_f32_bf16<<<(n4w + 255) / 256, 256>>>(W_in, win_bf, n4w);
    int n4c = NCAT * D_MODEL / 4;
    build_wcat<<<(n4c + 255) / 256, 256>>>(W_dt, W_B, W_C, wcat_bf);

    // 1) x_ssm = x @ W_in[:768].T  (z half is dead code); bf16 out
    dim3 g1(D_MODEL / 128, M_ROWS / 128);
    gemm_bf16<<<g1, 256, GEMM_SMEM>>>(xbf, win_bf, nullptr, xssm_bf, nullptr, nullptr, nullptr, 0);

    // 2) depthwise causal conv + bias + SiLU (bf16 -> bf16)
    int quads = M_ROWS * D_MODEL / 4;
    conv_silu_bf16<<<(quads + 255) / 256, 256>>>(xssm_bf, conv_w, conv_b, xconv_bf);

    // 3) fused: dt = softplus(xconv @ W_dt.T + b_dt); Bm = xconv @ W_B.T; Cm = xconv @ W_C.T
    dim3 g2(NCAT / 128, M_ROWS / 128);
    gemm_bf16<<<g2, 256, GEMM_SMEM>>>(xconv_bf, wcat_bf, b_dt, nullptr, dtb, Bm, Cm, 1);

    // 4-6) chunked associative scan
    dim3 scan_grid(D_MODEL / 256, NCH, B_SZ);
    scan_pass1<<<scan_grid, 256>>>(dtb, Bm, x, A_log, hend, Pp);
    scan_combine<<<(B_SZ * D_STATE * D_MODEL + 255) / 256, 256>>>(hend, Pp, sin_);
    scan_pass3<<<scan_grid, 256>>>(dtb, Bm, Cm, x, A_log, D_par, sin_, y);
}

// round 7
// speedup vs baseline: 1.2396x; 1.2396x over previous
#include <cuda_runtime.h>
#include <cuda_bf16.h>
#include <cstdint>

// Problem constants
#define B_SZ 8
#define T_SEQ 2048
#define D_MODEL 768
#define D_STATE 16
#define D_CONV 4
#define M_ROWS (B_SZ * T_SEQ)          // 16384
#define NCH 16                          // scan chunks
#define TCH (T_SEQ / NCH)               // 128 steps per chunk
#define NCAT 896                        // padded fused-GEMM2 N (768 dt + 16 B + 16 C + 96 pad)

// ---------------- scratch (__device__ globals; no runtime alloc) -------------
__device__ __nv_bfloat16 g_xbf     [M_ROWS * D_MODEL];
__device__ __nv_bfloat16 g_xssm_bf [M_ROWS * D_MODEL];
__device__ __nv_bfloat16 g_xconv_bf[M_ROWS * D_MODEL];
__device__ __nv_bfloat16 g_Win_bf  [D_MODEL * D_MODEL];
__device__ __nv_bfloat16 g_Wcat_bf [NCAT * D_MODEL];
__device__ float g_dt   [M_ROWS * D_MODEL];
__device__ __nv_bfloat16 g_Bmbf [M_ROWS * D_STATE];
__device__ __nv_bfloat16 g_Cmbf [M_ROWS * D_STATE];
__device__ float g_hend [B_SZ * NCH * D_STATE * D_MODEL];
__device__ float g_Pp   [B_SZ * NCH * D_STATE * D_MODEL];
__device__ float g_sin  [B_SZ * NCH * D_STATE * D_MODEL];

// ============================ PTX helpers =====================================
__device__ __forceinline__ uint32_t smem_u32(const void* p) {
    uint32_t a;
    asm("{ .reg .u64 t; cvta.to.shared.u64 t, %1; cvt.u32.u64 %0, t; }" : "=r"(a) : "l"(p));
    return a;
}
__device__ __forceinline__ void ldsm_x4(uint32_t addr, uint32_t& r0, uint32_t& r1,
                                        uint32_t& r2, uint32_t& r3) {
    asm volatile("ldmatrix.sync.aligned.m8n8.x4.shared.b16 {%0,%1,%2,%3}, [%4];"
                 : "=r"(r0), "=r"(r1), "=r"(r2), "=r"(r3) : "r"(addr));
}
__device__ __forceinline__ void mma_bf16(float* c,
                                         uint32_t a0, uint32_t a1, uint32_t a2, uint32_t a3,
                                         uint32_t b0, uint32_t b1) {
    asm volatile("mma.sync.aligned.m16n8k16.row.col.f32.bf16.bf16.f32 "
                 "{%0,%1,%2,%3}, {%4,%5,%6,%7}, {%8,%9}, {%0,%1,%2,%3};"
                 : "+f"(c[0]), "+f"(c[1]), "+f"(c[2]), "+f"(c[3])
                 : "r"(a0), "r"(a1), "r"(a2), "r"(a3), "r"(b0), "r"(b1));
}
__device__ __forceinline__ __nv_bfloat16 f2bf(float x) { return __float2bfloat16_rn(x); }

#define CP16(dst, src) \
    asm volatile("cp.async.cg.shared.global [%0], [%1], 16;" :: "r"(dst), "l"(src) : "memory")
#define CP_COMMIT()  asm volatile("cp.async.commit_group;" ::: "memory")
#define CP_WAIT1()   asm volatile("cp.async.wait_group 1;" ::: "memory")

// ===================== bf16 mma.sync GEMM (round-5 validated config) ==========
// C[M, N] = A[M, 768](bf16) * W[N, 768](bf16)^T, fp32 accumulate.
// tile 128x128, BK=32, 3-stage cp.async pipeline (dynamic smem). 8 warps, 64x32 each.
// mode 0: write bf16 to outBF (no act).
// mode 1: fused epilogue: cols <768 -> softplus(v + bias) into outDT (fp32);
//         cols 768..783 -> Bm (bf16); 784..799 -> Cm (bf16); >=800 discard.
#define GK 768
#define CHKB 32
#define NKB (GK / CHKB)                 // 24
#define SRB 40                          // 32 + 8 pad bf16 (80B row; LDSM conflict-free)
#define ROWB (SRB * 2)                  // 80 bytes per smem row
#define MATB (128 * ROWB)               // 10240 bytes per matrix per stage
#define STGB (2 * MATB)                 // 20480 bytes per stage (A + W)
#define GEMM_SMEM (3 * STGB)            // 61440

__global__ __launch_bounds__(256, 2)
void gemm_bf16(const __nv_bfloat16* __restrict__ A, const __nv_bfloat16* __restrict__ W,
               const float* __restrict__ bias, __nv_bfloat16* __restrict__ outBF,
               float* __restrict__ outDT, __nv_bfloat16* __restrict__ Bm,
               __nv_bfloat16* __restrict__ Cm, int mode)
{
    extern __shared__ __align__(16) char smem_raw[];
    const uint32_t sbase = smem_u32(smem_raw);

    const int tid  = threadIdx.x;
    const int wid  = tid >> 5;
    const int lane = tid & 31;
    const int bn   = blockIdx.x * 128;
    const int bm   = blockIdx.y * 128;
    const int wm   = (wid & 1) * 64;
    const int wn   = (wid >> 1) * 32;

    float acc[4][4][4];
    #pragma unroll
    for (int i = 0; i < 4; i++)
        #pragma unroll
        for (int j = 0; j < 4; j++)
            #pragma unroll
            for (int c = 0; c < 4; c++) acc[i][j][c] = 0.f;

    // cp.async pattern: per chunk per matrix 128 rows x 64B = 512 x 16B; 2/thread/matrix
    const int r0 = tid >> 2;              // 0..63
    const int c8 = (tid & 3) * 8;         // bf16 elem offset 0,8,16,24
    const __nv_bfloat16* Aptr = A + (size_t)(bm + r0) * GK + c8;
    const __nv_bfloat16* Wptr = W + (size_t)(bn + r0) * GK + c8;
    const size_t gstep = (size_t)64 * GK;

    const uint32_t dA0 = sbase + (uint32_t)(r0 * ROWB + c8 * 2);
    const uint32_t dW0 = dA0 + MATB;

    auto issue = [&](int k) {
        uint32_t off = (uint32_t)(k % 3) * STGB;
        const __nv_bfloat16* a0 = Aptr + (size_t)k * CHKB;
        const __nv_bfloat16* w0 = Wptr + (size_t)k * CHKB;
        CP16(dA0 + off,                 a0);
        CP16(dA0 + off + 64u * ROWB,    a0 + gstep);
        CP16(dW0 + off,                 w0);
        CP16(dW0 + off + 64u * ROWB,    w0 + gstep);
        CP_COMMIT();
    };

    // ldmatrix lane addressing (validated round 4)
    const int arow = lane & 15;                       // A: rows m0..15
    const int ak   = (lane >> 4) * 8;                 // A: k half
    const int brow = ((lane >> 4) * 8) + (lane & 7);  // B: n row within 16
    const int bk   = ((lane >> 3) & 1) * 8;           // B: k half

    const uint32_t aAddr0 = sbase + (uint32_t)((wm + arow) * ROWB + ak * 2);
    const uint32_t bAddr0 = sbase + MATB + (uint32_t)((wn + brow) * ROWB + bk * 2);

    issue(0);
    issue(1);

    for (int k = 0; k < NKB; k++) {
        CP_WAIT1();
        __syncthreads();
        if (k + 2 < NKB) issue(k + 2);

        const uint32_t off = (uint32_t)(k % 3) * STGB;
        #pragma unroll
        for (int ks = 0; ks < 2; ks++) {
            const uint32_t koff = off + (uint32_t)(ks * 32);   // 16 bf16 = 32 bytes
            uint32_t bf[4][2];
            ldsm_x4(bAddr0 + koff,               bf[0][0], bf[0][1], bf[1][0], bf[1][1]);
            ldsm_x4(bAddr0 + koff + 16u * ROWB,  bf[2][0], bf[2][1], bf[3][0], bf[3][1]);
            #pragma unroll
            for (int mf = 0; mf < 4; mf++) {
                uint32_t a0, a1, a2, a3;
                ldsm_x4(aAddr0 + koff + (uint32_t)(mf * 16 * ROWB), a0, a1, a2, a3);
                #pragma unroll
                for (int nf = 0; nf < 4; nf++)
                    mma_bf16(acc[mf][nf], a0, a1, a2, a3, bf[nf][0], bf[nf][1]);
            }
        }
    }

    // epilogue: c0/c1 = (row, col/col+1); c2/c3 = row+8
    const int erow = lane >> 2;
    const int ecol = (lane & 3) * 2;
    #pragma unroll
    for (int mf = 0; mf < 4; mf++) {
        int row = bm + wm + mf * 16 + erow;
        #pragma unroll
        for (int nf = 0; nf < 4; nf++) {
            int col = bn + wn + nf * 8 + ecol;
            float v0 = acc[mf][nf][0], v1 = acc[mf][nf][1];
            float v2 = acc[mf][nf][2], v3 = acc[mf][nf][3];
            if (mode == 0) {
                __nv_bfloat162 p0 = { f2bf(v0), f2bf(v1) };
                __nv_bfloat162 p1 = { f2bf(v2), f2bf(v3) };
                *reinterpret_cast<__nv_bfloat162*>(outBF + (size_t)row * D_MODEL + col)       = p0;
                *reinterpret_cast<__nv_bfloat162*>(outBF + (size_t)(row + 8) * D_MODEL + col) = p1;
            } else if (col < 768) {
                float b0 = bias[col], b1 = bias[col + 1];
                v0 += b0; v1 += b1; v2 += b0; v3 += b1;
                v0 = (v0 > 20.f) ? v0 : log1pf(__expf(v0));
                v1 = (v1 > 20.f) ? v1 : log1pf(__expf(v1));
                v2 = (v2 > 20.f) ? v2 : log1pf(__expf(v2));
                v3 = (v3 > 20.f) ? v3 : log1pf(__expf(v3));
                *reinterpret_cast<float2*>(outDT + (size_t)row * D_MODEL + col)       = make_float2(v0, v1);
                *reinterpret_cast<float2*>(outDT + (size_t)(row + 8) * D_MODEL + col) = make_float2(v2, v3);
            } else if (col < 784) {
                int n = col - 768;
                __nv_bfloat162 p0 = { f2bf(v0), f2bf(v1) };
                __nv_bfloat162 p1 = { f2bf(v2), f2bf(v3) };
                *reinterpret_cast<__nv_bfloat162*>(Bm + (size_t)row * D_STATE + n)       = p0;
                *reinterpret_cast<__nv_bfloat162*>(Bm + (size_t)(row + 8) * D_STATE + n) = p1;
            } else if (col < 800) {
                int n = col - 784;
                __nv_bfloat162 p0 = { f2bf(v0), f2bf(v1) };
                __nv_bfloat162 p1 = { f2bf(v2), f2bf(v3) };
                *reinterpret_cast<__nv_bfloat162*>(Cm + (size_t)row * D_STATE + n)       = p0;
                *reinterpret_cast<__nv_bfloat162*>(Cm + (size_t)(row + 8) * D_STATE + n) = p1;
            }
        }
    }
}

// ---------------- fp32 -> bf16 bulk convert ----------------------------------
__global__ void cvt_f32_bf16(const float* __restrict__ in, __nv_bfloat16* __restrict__ out, int n4)
{
    int idx = blockIdx.x * blockDim.x + threadIdx.x;
    if (idx >= n4) return;
    float4 v = reinterpret_cast<const float4*>(in)[idx];
    __nv_bfloat162 lo = { f2bf(v.x), f2bf(v.y) };
    __nv_bfloat162 hi = { f2bf(v.z), f2bf(v.w) };
    uint2 u = { *reinterpret_cast<uint32_t*>(&lo), *reinterpret_cast<uint32_t*>(&hi) };
    reinterpret_cast<uint2*>(out)[idx] = u;
}

// ---------------- build concatenated weight (bf16) ---------------------------
__global__ void build_wcat(const float* __restrict__ W_dt, const float* __restrict__ W_B,
                           const float* __restrict__ W_C, __nv_bfloat16* __restrict__ out)
{
    int idx = blockIdx.x * blockDim.x + threadIdx.x;
    if (idx >= NCAT * D_MODEL / 4) return;
    int r  = idx / (D_MODEL / 4);
    int c4 = (idx % (D_MODEL / 4)) * 4;
    float4 v = make_float4(0.f, 0.f, 0.f, 0.f);
    if (r < 768)      v = *reinterpret_cast<const float4*>(W_dt + (size_t)r * D_MODEL + c4);
    else if (r < 784) v = *reinterpret_cast<const float4*>(W_B + (size_t)(r - 768) * D_MODEL + c4);
    else if (r < 800) v = *reinterpret_cast<const float4*>(W_C + (size_t)(r - 784) * D_MODEL + c4);
    __nv_bfloat162 lo = { f2bf(v.x), f2bf(v.y) };
    __nv_bfloat162 hi = { f2bf(v.z), f2bf(v.w) };
    uint2 u = { *reinterpret_cast<uint32_t*>(&lo), *reinterpret_cast<uint32_t*>(&hi) };
    reinterpret_cast<uint2*>(out)[idx] = u;
}

// ---------------- depthwise causal conv (K=4) + bias + SiLU, bf16 in/out -----
__global__ void conv_silu_bf16(const __nv_bfloat16* __restrict__ xin,
                               const float* __restrict__ cw,
                               const float* __restrict__ cb,
                               __nv_bfloat16* __restrict__ out)
{
    int idx = blockIdx.x * blockDim.x + threadIdx.x;   // pair index
    if (idx >= M_ROWS * D_MODEL / 2) return;
    int d2 = idx % (D_MODEL / 2);
    int t  = (idx / (D_MODEL / 2)) % T_SEQ;
    int d  = d2 * 2;

    float a0 = cb[d], a1 = cb[d + 1];
    #pragma unroll
    for (int k = 0; k < D_CONV; k++) {
        int rel = k - (D_CONV - 1);
        if (t + rel >= 0) {
            __nv_bfloat162 xv = reinterpret_cast<const __nv_bfloat162*>(xin)[idx + rel * (D_MODEL / 2)];
            float f0 = __bfloat162float(xv.x), f1 = __bfloat162float(xv.y);
            a0 = fmaf(f0, cw[d * D_CONV + k], a0);
            a1 = fmaf(f1, cw[(d + 1) * D_CONV + k], a1);
        }
    }
    float s0 = a0 / (1.f + __expf(-a0));
    float s1 = a1 / (1.f + __expf(-a1));
    __nv_bfloat162 o = { f2bf(s0), f2bf(s1) };
    reinterpret_cast<__nv_bfloat162*>(out)[idx] = o;
}

// ---------------- scan helpers ------------------------------------------------
__device__ __forceinline__ void load_A_and_mode(const float* __restrict__ A_log,
                                                int d, float* A, bool& fast)
{
    #pragma unroll
    for (int n = 0; n < D_STATE; n++) A[n] = -__expf(A_log[d * D_STATE + n]);
    fast = true;
    #pragma unroll
    for (int n = 1; n < D_STATE; n++)
        fast = fast && (fabsf(A[n] - (float)(n + 1) * A[0]) <= 1e-4f * fabsf(A[n]));
}

// scalar powers: pw[n] = p^(n+1)
__device__ __forceinline__ void powers16(float p1, float* pw)
{
    float p2 = p1 * p1, p4 = p2 * p2, p8 = p4 * p4;
    pw[0] = p1;        pw[1] = p2;        pw[2] = p2 * p1;   pw[3] = p4;
    pw[4] = p4 * p1;   pw[5] = p4 * p2;   pw[6] = p4 * pw[2]; pw[7] = p8;
    pw[8] = p8 * p1;   pw[9] = p8 * p2;   pw[10] = p8 * pw[2]; pw[11] = p8 * p4;
    pw[12] = p8 * pw[4]; pw[13] = p8 * pw[5]; pw[14] = p8 * pw[6]; pw[15] = p8 * p8;
}

// packed bf16x2 powers: pw2[k] = (p^(2k+1), p^(2k+2))
__device__ __forceinline__ void powers16_h2(float p, __nv_bfloat162* pw2)
{
    float p2 = p * p;
    __nv_bfloat162 st = __floats2bfloat162_rn(p2, p2);
    pw2[0] = __floats2bfloat162_rn(p, p2);
    #pragma unroll
    for (int k = 1; k < 8; k++) pw2[k] = __hmul2(pw2[k - 1], st);
}

// pass 1: per-chunk local scan from h=0; emit end-state and cumulative decay
__global__ __launch_bounds__(256)
void scan_pass1(const float* __restrict__ dt, const __nv_bfloat16* __restrict__ Bm,
                const float* __restrict__ x,  const float* __restrict__ A_log,
                float* __restrict__ hend, float* __restrict__ Pp)
{
    __shared__ __align__(16) __nv_bfloat162 sB[TCH * 8];
    int d  = blockIdx.x * blockDim.x + threadIdx.x;
    int ch = blockIdx.y;
    int b  = blockIdx.z;
    int t0 = ch * TCH;

    {
        const uint4* src = reinterpret_cast<const uint4*>(Bm + ((size_t)(b * T_SEQ + t0)) * D_STATE);
        uint4* dst = reinterpret_cast<uint4*>(sB);
        for (int i = threadIdx.x; i < TCH * D_STATE / 8; i += blockDim.x) dst[i] = src[i];
    }
    __syncthreads();

    float A[D_STATE]; bool fast;
    load_A_and_mode(A_log, d, A, fast);

    const float* dtp = dt + ((size_t)(b * T_SEQ + t0)) * D_MODEL + d;
    const float* xp  = x  + ((size_t)(b * T_SEQ + t0)) * D_MODEL + d;
    size_t base = ((size_t)(b * NCH + ch) * D_STATE) * D_MODEL + d;

    if (fast) {
        const float A0 = A[0];
        __nv_bfloat162 h2[8];
        #pragma unroll
        for (int k = 0; k < 8; k++) h2[k] = __floats2bfloat162_rn(0.f, 0.f);
        float S = 0.f;
        for (int t = 0; t < TCH; t += 4) {
            float dtv[4], xv[4];
            #pragma unroll
            for (int j = 0; j < 4; j++) {
                dtv[j] = dtp[(size_t)(t + j) * D_MODEL];
                xv[j]  = xp [(size_t)(t + j) * D_MODEL];
            }
            #pragma unroll
            for (int j = 0; j < 4; j++) {
                float u = xv[j] * dtv[j];
                S += dtv[j];
                __nv_bfloat162 pw2[8];
                powers16_h2(__expf(A0 * dtv[j]), pw2);
                __nv_bfloat162 u2 = __float2bfloat162_rn(u);
                const uint4* brow = reinterpret_cast<const uint4*>(sB + (t + j) * 8);
                uint4 br0 = brow[0], br1 = brow[1];
                const __nv_bfloat162* b2 = reinterpret_cast<const __nv_bfloat162*>(&br0);
                const __nv_bfloat162* b2b = reinterpret_cast<const __nv_bfloat162*>(&br1);
                #pragma unroll
                for (int k = 0; k < 4; k++)
                    h2[k] = __hfma2(h2[k], pw2[k], __hmul2(u2, b2[k]));
                #pragma unroll
                for (int k = 0; k < 4; k++)
                    h2[4 + k] = __hfma2(h2[4 + k], pw2[4 + k], __hmul2(u2, b2b[k]));
            }
        }
        float pw[16];
        powers16(__expf(A0 * S), pw);
        #pragma unroll
        for (int k = 0; k < 8; k++) {
            float2 hf = __bfloat1622float2(h2[k]);
            hend[base + (size_t)(2 * k)     * D_MODEL] = hf.x;
            hend[base + (size_t)(2 * k + 1) * D_MODEL] = hf.y;
            Pp  [base + (size_t)(2 * k)     * D_MODEL] = pw[2 * k];
            Pp  [base + (size_t)(2 * k + 1) * D_MODEL] = pw[2 * k + 1];
        }
    } else {
        float h[D_STATE], P[D_STATE];
        #pragma unroll
        for (int n = 0; n < D_STATE; n++) { h[n] = 0.f; P[n] = 1.f; }
        const __nv_bfloat16* sBs = reinterpret_cast<const __nv_bfloat16*>(sB);
        for (int t = 0; t < TCH; t++) {
            float dtv = dtp[(size_t)t * D_MODEL];
            float xv  = xp [(size_t)t * D_MODEL];
            float u   = xv * dtv;
            #pragma unroll
            for (int n = 0; n < D_STATE; n++) {
                float pw = __expf(A[n] * dtv);
                h[n] = fmaf(h[n], pw, u * __bfloat162float(sBs[t * D_STATE + n]));
                P[n] *= pw;
            }
        }
        #pragma unroll
        for (int n = 0; n < D_STATE; n++) {
            hend[base + (size_t)n * D_MODEL] = h[n];
            Pp  [base + (size_t)n * D_MODEL] = P[n];
        }
    }
}

// pass 2: sequential combine over chunks -> chunk-entry states
__global__ void scan_combine(const float* __restrict__ hend, const float* __restrict__ Pp,
                             float* __restrict__ sin_)
{
    int idx = blockIdx.x * blockDim.x + threadIdx.x;
    if (idx >= B_SZ * D_STATE * D_MODEL) return;
    int d = idx % D_MODEL;
    int n = (idx / D_MODEL) % D_STATE;
    int b = idx / (D_MODEL * D_STATE);

    float s = 0.f;
    for (int ch = 0; ch < NCH; ch++) {
        size_t off = ((size_t)(b * NCH + ch) * D_STATE + n) * D_MODEL + d;
        sin_[off] = s;
        s = fmaf(Pp[off], s, hend[off]);
    }
}

// pass 3: replay chunks with correct entry state; emit y + residual
__global__ __launch_bounds__(256)
void scan_pass3(const float* __restrict__ dt, const __nv_bfloat16* __restrict__ Bm,
                const __nv_bfloat16* __restrict__ Cm, const float* __restrict__ x,
                const float* __restrict__ A_log, const float* __restrict__ Dp,
                const float* __restrict__ sin_, float* __restrict__ y)
{
    __shared__ __align__(16) __nv_bfloat162 sB[TCH * 8];
    __shared__ __align__(16) __nv_bfloat162 sC[TCH * 8];
    int d  = blockIdx.x * blockDim.x + threadIdx.x;
    int ch = blockIdx.y;
    int b  = blockIdx.z;
    int t0 = ch * TCH;

    {
        const uint4* srcB = reinterpret_cast<const uint4*>(Bm + ((size_t)(b * T_SEQ + t0)) * D_STATE);
        const uint4* srcC = reinterpret_cast<const uint4*>(Cm + ((size_t)(b * T_SEQ + t0)) * D_STATE);
        uint4* dB = reinterpret_cast<uint4*>(sB);
        uint4* dC = reinterpret_cast<uint4*>(sC);
        for (int i = threadIdx.x; i < TCH * D_STATE / 8; i += blockDim.x) { dB[i] = srcB[i]; dC[i] = srcC[i]; }
    }
    __syncthreads();

    float A[D_STATE]; bool fast;
    load_A_and_mode(A_log, d, A, fast);

    size_t base = ((size_t)(b * NCH + ch) * D_STATE) * D_MODEL + d;
    float dpar = Dp[d];
    const float* dtp = dt + ((size_t)(b * T_SEQ + t0)) * D_MODEL + d;
    const float* xp  = x  + ((size_t)(b * T_SEQ + t0)) * D_MODEL + d;
    float* yp        = y  + ((size_t)(b * T_SEQ + t0)) * D_MODEL + d;

    if (fast) {
        const float A0 = A[0];
        __nv_bfloat162 h2[8];
        #pragma unroll
        for (int k = 0; k < 8; k++)
            h2[k] = __floats2bfloat162_rn(sin_[base + (size_t)(2 * k) * D_MODEL],
                                          sin_[base + (size_t)(2 * k + 1) * D_MODEL]);

        for (int t = 0; t < TCH; t += 4) {
            float dtv[4], xv[4];
            #pragma unroll
            for (int j = 0; j < 4; j++) {
                dtv[j] = dtp[(size_t)(t + j) * D_MODEL];
                xv[j]  = xp [(size_t)(t + j) * D_MODEL];
            }
            float yv[4];
            #pragma unroll
            for (int j = 0; j < 4; j++) {
                float u = xv[j] * dtv[j];
                __nv_bfloat162 pw2[8];
                powers16_h2(__expf(A0 * dtv[j]), pw2);
                __nv_bfloat162 u2 = __float2bfloat162_rn(u);
                const uint4* browp = reinterpret_cast<const uint4*>(sB + (t + j) * 8);
                const uint4* crowp = reinterpret_cast<const uint4*>(sC + (t + j) * 8);
                uint4 br0 = browp[0], br1 = browp[1];
                uint4 cr0 = crowp[0], cr1 = crowp[1];
                const __nv_bfloat162* b2a = reinterpret_cast<const __nv_bfloat162*>(&br0);
                const __nv_bfloat162* b2b = reinterpret_cast<const __nv_bfloat162*>(&br1);
                const __nv_bfloat162* c2a = reinterpret_cast<const __nv_bfloat162*>(&cr0);
                const __nv_bfloat162* c2b = reinterpret_cast<const __nv_bfloat162*>(&cr1);
                __nv_bfloat162 acc2 = __floats2bfloat162_rn(0.f, 0.f);
                #pragma unroll
                for (int k = 0; k < 4; k++) {
                    h2[k] = __hfma2(h2[k], pw2[k], __hmul2(u2, b2a[k]));
                    acc2  = __hfma2(h2[k], c2a[k], acc2);
                }
                #pragma unroll
                for (int k = 0; k < 4; k++) {
                    h2[4 + k] = __hfma2(h2[4 + k], pw2[4 + k], __hmul2(u2, b2b[k]));
                    acc2      = __hfma2(h2[4 + k], c2b[k], acc2);
                }
                float2 af = __bfloat1622float2(acc2);
                yv[j] = fmaf(xv[j], dpar, af.x + af.y);
            }
            #pragma unroll
            for (int j = 0; j < 4; j++)
                yp[(size_t)(t + j) * D_MODEL] = yv[j];
        }
    } else {
        float h[D_STATE];
        #pragma unroll
        for (int n = 0; n < D_STATE; n++) h[n] = sin_[base + (size_t)n * D_MODEL];
        const __nv_bfloat16* sBs = reinterpret_cast<const __nv_bfloat16*>(sB);
        const __nv_bfloat16* sCs = reinterpret_cast<const __nv_bfloat16*>(sC);
        for (int t = 0; t < TCH; t++) {
            float dtv = dtp[(size_t)t * D_MODEL];
            float xv  = xp [(size_t)t * D_MODEL];
            float u   = xv * dtv;
            float acc = 0.f;
            #pragma unroll
            for (int n = 0; n < D_STATE; n++) {
                float pw = __expf(A[n] * dtv);
                h[n] = fmaf(h[n], pw, u * __bfloat162float(sBs[t * D_STATE + n]));
                acc  = fmaf(h[n], __bfloat162float(sCs[t * D_STATE + n]), acc);
            }
            yp[(size_t)t * D_MODEL] = fmaf(xv, dpar, acc);
        }
    }
}

// ---------------- launch ------------------------------------------------------
extern "C" void kernel_launch(void* const* d_in, const int* in_sizes, int n_in,
                              void* d_out, int out_size)
{
    const float* x      = (const float*)d_in[0];
    const float* W_in   = (const float*)d_in[1];
    const float* conv_w = (const float*)d_in[2];
    const float* conv_b = (const float*)d_in[3];
    const float* W_dt   = (const float*)d_in[4];
    const float* b_dt   = (const float*)d_in[5];
    const float* A_log  = (const float*)d_in[6];
    const float* D_par  = (const float*)d_in[7];
    const float* W_B    = (const float*)d_in[8];
    const float* W_C    = (const float*)d_in[9];
    float* y = (float*)d_out;

    __nv_bfloat16 *xbf, *xssm_bf, *xconv_bf, *win_bf, *wcat_bf, *Bmbf, *Cmbf;
    float *dtb, *hend, *Pp, *sin_;
    cudaGetSymbolAddress((void**)&xbf,      g_xbf);
    cudaGetSymbolAddress((void**)&xssm_bf,  g_xssm_bf);
    cudaGetSymbolAddress((void**)&xconv_bf, g_xconv_bf);
    cudaGetSymbolAddress((void**)&win_bf,   g_Win_bf);
    cudaGetSymbolAddress((void**)&wcat_bf,  g_Wcat_bf);
    cudaGetSymbolAddress((void**)&dtb,   g_dt);
    cudaGetSymbolAddress((void**)&Bmbf,  g_Bmbf);
    cudaGetSymbolAddress((void**)&Cmbf,  g_Cmbf);
    cudaGetSymbolAddress((void**)&hend,  g_hend);
    cudaGetSymbolAddress((void**)&Pp,    g_Pp);
    cudaGetSymbolAddress((void**)&sin_,  g_sin);

    cudaFuncSetAttribute(gemm_bf16, cudaFuncAttributeMaxDynamicSharedMemorySize, GEMM_SMEM);

    // 0) precision prep: x -> bf16; W_in[:768] -> bf16; [W_dt; W_B; W_C; 0] -> bf16
    int n4x = M_ROWS * D_MODEL / 4;
    cvt_f32_bf16<<<(n4x + 255) / 256, 256>>>(x, xbf, n4x);
    int n4w = D_MODEL * D_MODEL / 4;
    cvt_f32_bf16<<<(n4w + 255) / 256, 256>>>(W_in, win_bf, n4w);
    int n4c = NCAT * D_MODEL / 4;
    build_wcat<<<(n4c + 255) / 256, 256>>>(W_dt, W_B, W_C, wcat_bf);

    // 1) x_ssm = x @ W_in[:768].T  (z half is dead code); bf16 out
    dim3 g1(D_MODEL / 128, M_ROWS / 128);
    gemm_bf16<<<g1, 256, GEMM_SMEM>>>(xbf, win_bf, nullptr, xssm_bf, nullptr, nullptr, nullptr, 0);

    // 2) depthwise causal conv + bias + SiLU (bf16 -> bf16)
    int pairs = M_ROWS * D_MODEL / 2;
    conv_silu_bf16<<<(pairs + 255) / 256, 256>>>(xssm_bf, conv_w, conv_b, xconv_bf);

    // 3) fused: dt = softplus(xconv @ W_dt.T + b_dt); Bm/Cm (bf16) = xconv @ W_B/C.T
    dim3 g2(NCAT / 128, M_ROWS / 128);
    gemm_bf16<<<g2, 256, GEMM_SMEM>>>(xconv_bf, wcat_bf, b_dt, nullptr, dtb, Bmbf, Cmbf, 1);

    // 4-6) chunked associative scan (bf16x2 packed states)
    dim3 scan_grid(D_MODEL / 256, NCH, B_SZ);
    scan_pass1<<<scan_grid, 256>>>(dtb, Bmbf, x, A_log, hend, Pp);
    scan_combine<<<(B_SZ * D_STATE * D_MODEL + 255) / 256, 256>>>(hend, Pp, sin_);
    scan_pass3<<<scan_grid, 256>>>(dtb, Bmbf, Cmbf, x, A_log, D_par, sin_, y);
}

// round 8
// speedup vs baseline: 1.2580x; 1.0149x over previous
#include <cuda_runtime.h>
#include <cuda_bf16.h>
#include <cstdint>

// Problem constants
#define B_SZ 8
#define T_SEQ 2048
#define D_MODEL 768
#define D_STATE 16
#define D_CONV 4
#define M_ROWS (B_SZ * T_SEQ)          // 16384
#define NCH 16                          // scan chunks
#define TCH (T_SEQ / NCH)               // 128 steps per chunk
#define NCAT 896                        // padded fused-GEMM2 N (768 dt + 16 B + 16 C + 96 pad)

// ---------------- scratch (__device__ globals; no runtime alloc) -------------
__device__ __nv_bfloat16 g_xbf     [M_ROWS * D_MODEL];
__device__ __nv_bfloat16 g_xssm_bf [M_ROWS * D_MODEL];
__device__ __nv_bfloat16 g_xconv_bf[M_ROWS * D_MODEL];
__device__ __nv_bfloat16 g_Win_bf  [D_MODEL * D_MODEL];
__device__ __nv_bfloat16 g_Wcat_bf [NCAT * D_MODEL];
__device__ __nv_bfloat16 g_dtbf [M_ROWS * D_MODEL];
__device__ __nv_bfloat16 g_pbf  [M_ROWS * D_MODEL];
__device__ __nv_bfloat16 g_Bmbf [M_ROWS * D_STATE];
__device__ __nv_bfloat16 g_Cmbf [M_ROWS * D_STATE];
__device__ float g_hend [B_SZ * NCH * D_STATE * D_MODEL];
__device__ float g_Pp   [B_SZ * NCH * D_STATE * D_MODEL];
__device__ float g_sin  [B_SZ * NCH * D_STATE * D_MODEL];

// ============================ PTX helpers =====================================
__device__ __forceinline__ uint32_t smem_u32(const void* p) {
    uint32_t a;
    asm("{ .reg .u64 t; cvta.to.shared.u64 t, %1; cvt.u32.u64 %0, t; }" : "=r"(a) : "l"(p));
    return a;
}
__device__ __forceinline__ void ldsm_x4(uint32_t addr, uint32_t& r0, uint32_t& r1,
                                        uint32_t& r2, uint32_t& r3) {
    asm volatile("ldmatrix.sync.aligned.m8n8.x4.shared.b16 {%0,%1,%2,%3}, [%4];"
                 : "=r"(r0), "=r"(r1), "=r"(r2), "=r"(r3) : "r"(addr));
}
__device__ __forceinline__ void mma_bf16(float* c,
                                         uint32_t a0, uint32_t a1, uint32_t a2, uint32_t a3,
                                         uint32_t b0, uint32_t b1) {
    asm volatile("mma.sync.aligned.m16n8k16.row.col.f32.bf16.bf16.f32 "
                 "{%0,%1,%2,%3}, {%4,%5,%6,%7}, {%8,%9}, {%0,%1,%2,%3};"
                 : "+f"(c[0]), "+f"(c[1]), "+f"(c[2]), "+f"(c[3])
                 : "r"(a0), "r"(a1), "r"(a2), "r"(a3), "r"(b0), "r"(b1));
}
__device__ __forceinline__ __nv_bfloat16 f2bf(float x) { return __float2bfloat16_rn(x); }

#define CP16(dst, src) \
    asm volatile("cp.async.cg.shared.global [%0], [%1], 16;" :: "r"(dst), "l"(src) : "memory")
#define CP_COMMIT()  asm volatile("cp.async.commit_group;" ::: "memory")
#define CP_WAIT1()   asm volatile("cp.async.wait_group 1;" ::: "memory")

// ===================== bf16 mma.sync GEMM (round-5 validated config) ==========
// C[M, N] = A[M, 768](bf16) * W[N, 768](bf16)^T, fp32 accumulate.
// tile 128x128, BK=32, 3-stage cp.async pipeline (dynamic smem). 8 warps, 64x32 each.
// mode 0: write bf16 to outBF (no act).
// mode 1: fused epilogue: cols <768 -> w = v + bias; dt = softplus(w) (bf16) and
//         p = 1/(1+e^w) = exp(-dt) (bf16, exact since A0 = -1);
//         cols 768..783 -> Bm (bf16); 784..799 -> Cm (bf16); >=800 discard.
#define GK 768
#define CHKB 32
#define NKB (GK / CHKB)                 // 24
#define SRB 40                          // 32 + 8 pad bf16 (80B row; LDSM conflict-free)
#define ROWB (SRB * 2)                  // 80 bytes per smem row
#define MATB (128 * ROWB)               // 10240 bytes per matrix per stage
#define STGB (2 * MATB)                 // 20480 bytes per stage (A + W)
#define GEMM_SMEM (3 * STGB)            // 61440

__global__ __launch_bounds__(256, 2)
void gemm_bf16(const __nv_bfloat16* __restrict__ A, const __nv_bfloat16* __restrict__ W,
               const float* __restrict__ bias, __nv_bfloat16* __restrict__ outBF,
               __nv_bfloat16* __restrict__ outDT, __nv_bfloat16* __restrict__ outP,
               __nv_bfloat16* __restrict__ Bm, __nv_bfloat16* __restrict__ Cm, int mode)
{
    extern __shared__ __align__(16) char smem_raw[];
    const uint32_t sbase = smem_u32(smem_raw);

    const int tid  = threadIdx.x;
    const int wid  = tid >> 5;
    const int lane = tid & 31;
    const int bn   = blockIdx.x * 128;
    const int bm   = blockIdx.y * 128;
    const int wm   = (wid & 1) * 64;
    const int wn   = (wid >> 1) * 32;

    float acc[4][4][4];
    #pragma unroll
    for (int i = 0; i < 4; i++)
        #pragma unroll
        for (int j = 0; j < 4; j++)
            #pragma unroll
            for (int c = 0; c < 4; c++) acc[i][j][c] = 0.f;

    // cp.async pattern: per chunk per matrix 128 rows x 64B = 512 x 16B; 2/thread/matrix
    const int r0 = tid >> 2;              // 0..63
    const int c8 = (tid & 3) * 8;         // bf16 elem offset 0,8,16,24
    const __nv_bfloat16* Aptr = A + (size_t)(bm + r0) * GK + c8;
    const __nv_bfloat16* Wptr = W + (size_t)(bn + r0) * GK + c8;
    const size_t gstep = (size_t)64 * GK;

    const uint32_t dA0 = sbase + (uint32_t)(r0 * ROWB + c8 * 2);
    const uint32_t dW0 = dA0 + MATB;

    auto issue = [&](int k) {
        uint32_t off = (uint32_t)(k % 3) * STGB;
        const __nv_bfloat16* a0 = Aptr + (size_t)k * CHKB;
        const __nv_bfloat16* w0 = Wptr + (size_t)k * CHKB;
        CP16(dA0 + off,                 a0);
        CP16(dA0 + off + 64u * ROWB,    a0 + gstep);
        CP16(dW0 + off,                 w0);
        CP16(dW0 + off + 64u * ROWB,    w0 + gstep);
        CP_COMMIT();
    };

    // ldmatrix lane addressing (validated round 4)
    const int arow = lane & 15;                       // A: rows m0..15
    const int ak   = (lane >> 4) * 8;                 // A: k half
    const int brow = ((lane >> 4) * 8) + (lane & 7);  // B: n row within 16
    const int bk   = ((lane >> 3) & 1) * 8;           // B: k half

    const uint32_t aAddr0 = sbase + (uint32_t)((wm + arow) * ROWB + ak * 2);
    const uint32_t bAddr0 = sbase + MATB + (uint32_t)((wn + brow) * ROWB + bk * 2);

    issue(0);
    issue(1);

    for (int k = 0; k < NKB; k++) {
        CP_WAIT1();
        __syncthreads();
        if (k + 2 < NKB) issue(k + 2);

        const uint32_t off = (uint32_t)(k % 3) * STGB;
        #pragma unroll
        for (int ks = 0; ks < 2; ks++) {
            const uint32_t koff = off + (uint32_t)(ks * 32);   // 16 bf16 = 32 bytes
            uint32_t bf[4][2];
            ldsm_x4(bAddr0 + koff,               bf[0][0], bf[0][1], bf[1][0], bf[1][1]);
            ldsm_x4(bAddr0 + koff + 16u * ROWB,  bf[2][0], bf[2][1], bf[3][0], bf[3][1]);
            #pragma unroll
            for (int mf = 0; mf < 4; mf++) {
                uint32_t a0, a1, a2, a3;
                ldsm_x4(aAddr0 + koff + (uint32_t)(mf * 16 * ROWB), a0, a1, a2, a3);
                #pragma unroll
                for (int nf = 0; nf < 4; nf++)
                    mma_bf16(acc[mf][nf], a0, a1, a2, a3, bf[nf][0], bf[nf][1]);
            }
        }
    }

    // epilogue: c0/c1 = (row, col/col+1); c2/c3 = row+8
    const int erow = lane >> 2;
    const int ecol = (lane & 3) * 2;
    #pragma unroll
    for (int mf = 0; mf < 4; mf++) {
        int row = bm + wm + mf * 16 + erow;
        #pragma unroll
        for (int nf = 0; nf < 4; nf++) {
            int col = bn + wn + nf * 8 + ecol;
            float v0 = acc[mf][nf][0], v1 = acc[mf][nf][1];
            float v2 = acc[mf][nf][2], v3 = acc[mf][nf][3];
            if (mode == 0) {
                __nv_bfloat162 p0 = { f2bf(v0), f2bf(v1) };
                __nv_bfloat162 p1 = { f2bf(v2), f2bf(v3) };
                *reinterpret_cast<__nv_bfloat162*>(outBF + (size_t)row * D_MODEL + col)       = p0;
                *reinterpret_cast<__nv_bfloat162*>(outBF + (size_t)(row + 8) * D_MODEL + col) = p1;
            } else if (col < 768) {
                float b0 = bias[col], b1 = bias[col + 1];
                float w0 = v0 + b0, w1 = v1 + b1, w2 = v2 + b0, w3 = v3 + b1;
                float e0 = __expf(w0), e1 = __expf(w1), e2 = __expf(w2), e3 = __expf(w3);
                float dt0 = (w0 > 20.f) ? w0 : log1pf(e0);
                float dt1 = (w1 > 20.f) ? w1 : log1pf(e1);
                float dt2 = (w2 > 20.f) ? w2 : log1pf(e2);
                float dt3 = (w3 > 20.f) ? w3 : log1pf(e3);
                float q0 = __fdividef(1.f, 1.f + e0);
                float q1 = __fdividef(1.f, 1.f + e1);
                float q2 = __fdividef(1.f, 1.f + e2);
                float q3 = __fdividef(1.f, 1.f + e3);
                __nv_bfloat162 d01 = { f2bf(dt0), f2bf(dt1) };
                __nv_bfloat162 d23 = { f2bf(dt2), f2bf(dt3) };
                __nv_bfloat162 q01 = { f2bf(q0), f2bf(q1) };
                __nv_bfloat162 q23 = { f2bf(q2), f2bf(q3) };
                *reinterpret_cast<__nv_bfloat162*>(outDT + (size_t)row * D_MODEL + col)       = d01;
                *reinterpret_cast<__nv_bfloat162*>(outDT + (size_t)(row + 8) * D_MODEL + col) = d23;
                *reinterpret_cast<__nv_bfloat162*>(outP + (size_t)row * D_MODEL + col)        = q01;
                *reinterpret_cast<__nv_bfloat162*>(outP + (size_t)(row + 8) * D_MODEL + col)  = q23;
            } else if (col < 784) {
                int n = col - 768;
                __nv_bfloat162 p0 = { f2bf(v0), f2bf(v1) };
                __nv_bfloat162 p1 = { f2bf(v2), f2bf(v3) };
                *reinterpret_cast<__nv_bfloat162*>(Bm + (size_t)row * D_STATE + n)       = p0;
                *reinterpret_cast<__nv_bfloat162*>(Bm + (size_t)(row + 8) * D_STATE + n) = p1;
            } else if (col < 800) {
                int n = col - 784;
                __nv_bfloat162 p0 = { f2bf(v0), f2bf(v1) };
                __nv_bfloat162 p1 = { f2bf(v2), f2bf(v3) };
                *reinterpret_cast<__nv_bfloat162*>(Cm + (size_t)row * D_STATE + n)       = p0;
                *reinterpret_cast<__nv_bfloat162*>(Cm + (size_t)(row + 8) * D_STATE + n) = p1;
            }
        }
    }
}

// ---------------- fp32 -> bf16 bulk convert ----------------------------------
__global__ void cvt_f32_bf16(const float* __restrict__ in, __nv_bfloat16* __restrict__ out, int n4)
{
    int idx = blockIdx.x * blockDim.x + threadIdx.x;
    if (idx >= n4) return;
    float4 v = reinterpret_cast<const float4*>(in)[idx];
    __nv_bfloat162 lo = { f2bf(v.x), f2bf(v.y) };
    __nv_bfloat162 hi = { f2bf(v.z), f2bf(v.w) };
    uint2 u = { *reinterpret_cast<uint32_t*>(&lo), *reinterpret_cast<uint32_t*>(&hi) };
    reinterpret_cast<uint2*>(out)[idx] = u;
}

// ---------------- build concatenated weight (bf16) ---------------------------
__global__ void build_wcat(const float* __restrict__ W_dt, const float* __restrict__ W_B,
                           const float* __restrict__ W_C, __nv_bfloat16* __restrict__ out)
{
    int idx = blockIdx.x * blockDim.x + threadIdx.x;
    if (idx >= NCAT * D_MODEL / 4) return;
    int r  = idx / (D_MODEL / 4);
    int c4 = (idx % (D_MODEL / 4)) * 4;
    float4 v = make_float4(0.f, 0.f, 0.f, 0.f);
    if (r < 768)      v = *reinterpret_cast<const float4*>(W_dt + (size_t)r * D_MODEL + c4);
    else if (r < 784) v = *reinterpret_cast<const float4*>(W_B + (size_t)(r - 768) * D_MODEL + c4);
    else if (r < 800) v = *reinterpret_cast<const float4*>(W_C + (size_t)(r - 784) * D_MODEL + c4);
    __nv_bfloat162 lo = { f2bf(v.x), f2bf(v.y) };
    __nv_bfloat162 hi = { f2bf(v.z), f2bf(v.w) };
    uint2 u = { *reinterpret_cast<uint32_t*>(&lo), *reinterpret_cast<uint32_t*>(&hi) };
    reinterpret_cast<uint2*>(out)[idx] = u;
}

// ---------------- depthwise causal conv (K=4) + bias + SiLU, bf16 in/out -----
__global__ void conv_silu_bf16(const __nv_bfloat16* __restrict__ xin,
                               const float* __restrict__ cw,
                               const float* __restrict__ cb,
                               __nv_bfloat16* __restrict__ out)
{
    int idx = blockIdx.x * blockDim.x + threadIdx.x;   // pair index
    if (idx >= M_ROWS * D_MODEL / 2) return;
    int d2 = idx % (D_MODEL / 2);
    int t  = (idx / (D_MODEL / 2)) % T_SEQ;
    int d  = d2 * 2;

    float a0 = cb[d], a1 = cb[d + 1];
    #pragma unroll
    for (int k = 0; k < D_CONV; k++) {
        int rel = k - (D_CONV - 1);
        if (t + rel >= 0) {
            __nv_bfloat162 xv = reinterpret_cast<const __nv_bfloat162*>(xin)[idx + rel * (D_MODEL / 2)];
            float f0 = __bfloat162float(xv.x), f1 = __bfloat162float(xv.y);
            a0 = fmaf(f0, cw[d * D_CONV + k], a0);
            a1 = fmaf(f1, cw[(d + 1) * D_CONV + k], a1);
        }
    }
    float s0 = a0 / (1.f + __expf(-a0));
    float s1 = a1 / (1.f + __expf(-a1));
    __nv_bfloat162 o = { f2bf(s0), f2bf(s1) };
    reinterpret_cast<__nv_bfloat162*>(out)[idx] = o;
}

// ---------------- scan helpers ------------------------------------------------
__device__ __forceinline__ void load_A_and_mode(const float* __restrict__ A_log,
                                                int d, float* A, bool& fast)
{
    #pragma unroll
    for (int n = 0; n < D_STATE; n++) A[n] = -__expf(A_log[d * D_STATE + n]);
    fast = true;
    // fast path requires A[n] = (n+1) * A0 AND A0 == -1 (p = exp(-dt) precomputed)
    fast = fast && (fabsf(A[0] + 1.f) <= 1e-5f);
    #pragma unroll
    for (int n = 1; n < D_STATE; n++)
        fast = fast && (fabsf(A[n] - (float)(n + 1) * A[0]) <= 1e-4f * fabsf(A[n]));
}

// scalar powers: pw[n] = p^(n+1)
__device__ __forceinline__ void powers16(float p1, float* pw)
{
    float p2 = p1 * p1, p4 = p2 * p2, p8 = p4 * p4;
    pw[0] = p1;        pw[1] = p2;        pw[2] = p2 * p1;   pw[3] = p4;
    pw[4] = p4 * p1;   pw[5] = p4 * p2;   pw[6] = p4 * pw[2]; pw[7] = p8;
    pw[8] = p8 * p1;   pw[9] = p8 * p2;   pw[10] = p8 * pw[2]; pw[11] = p8 * p4;
    pw[12] = p8 * pw[4]; pw[13] = p8 * pw[5]; pw[14] = p8 * pw[6]; pw[15] = p8 * p8;
}

// packed bf16x2 powers from bf16 base: pw2[k] = (p^(2k+1), p^(2k+2))
__device__ __forceinline__ void powers16_h2b(__nv_bfloat16 p, __nv_bfloat162* pw2)
{
    __nv_bfloat16 psq = __hmul(p, p);
    __nv_bfloat162 st = { psq, psq };
    pw2[0].x = p; pw2[0].y = psq;
    #pragma unroll
    for (int k = 1; k < 8; k++) pw2[k] = __hmul2(pw2[k - 1], st);
}

// pass 1: per-chunk local scan from h=0; emit end-state and cumulative decay
__global__ __launch_bounds__(256)
void scan_pass1(const __nv_bfloat16* __restrict__ dt, const __nv_bfloat16* __restrict__ pdec,
                const __nv_bfloat16* __restrict__ Bm, const __nv_bfloat16* __restrict__ x,
                const float* __restrict__ A_log,
                float* __restrict__ hend, float* __restrict__ Pp)
{
    __shared__ __align__(16) __nv_bfloat162 sB[TCH * 8];
    int d  = blockIdx.x * blockDim.x + threadIdx.x;
    int ch = blockIdx.y;
    int b  = blockIdx.z;
    int t0 = ch * TCH;

    {
        const uint4* src = reinterpret_cast<const uint4*>(Bm + ((size_t)(b * T_SEQ + t0)) * D_STATE);
        uint4* dst = reinterpret_cast<uint4*>(sB);
        for (int i = threadIdx.x; i < TCH * D_STATE / 8; i += blockDim.x) dst[i] = src[i];
    }
    __syncthreads();

    float A[D_STATE]; bool fast;
    load_A_and_mode(A_log, d, A, fast);

    const __nv_bfloat16* dtp = dt   + ((size_t)(b * T_SEQ + t0)) * D_MODEL + d;
    const __nv_bfloat16* pp  = pdec + ((size_t)(b * T_SEQ + t0)) * D_MODEL + d;
    const __nv_bfloat16* xp  = x    + ((size_t)(b * T_SEQ + t0)) * D_MODEL + d;
    size_t base = ((size_t)(b * NCH + ch) * D_STATE) * D_MODEL + d;

    if (fast) {
        const float A0 = A[0];
        __nv_bfloat162 h2[8];
        #pragma unroll
        for (int k = 0; k < 8; k++) h2[k] = __floats2bfloat162_rn(0.f, 0.f);
        float S = 0.f;
        for (int t = 0; t < TCH; t += 4) {
            __nv_bfloat16 dtv[4], pv[4], xv[4];
            #pragma unroll
            for (int j = 0; j < 4; j++) {
                dtv[j] = dtp[(size_t)(t + j) * D_MODEL];
                pv[j]  = pp [(size_t)(t + j) * D_MODEL];
                xv[j]  = xp [(size_t)(t + j) * D_MODEL];
            }
            #pragma unroll
            for (int j = 0; j < 4; j++) {
                float dtf = __bfloat162float(dtv[j]);
                float u   = __bfloat162float(xv[j]) * dtf;
                S += dtf;
                __nv_bfloat162 pw2[8];
                powers16_h2b(pv[j], pw2);
                __nv_bfloat162 u2 = __float2bfloat162_rn(u);
                const uint4* brow = reinterpret_cast<const uint4*>(sB + (t + j) * 8);
                uint4 br0 = brow[0], br1 = brow[1];
                const __nv_bfloat162* b2a = reinterpret_cast<const __nv_bfloat162*>(&br0);
                const __nv_bfloat162* b2b = reinterpret_cast<const __nv_bfloat162*>(&br1);
                #pragma unroll
                for (int k = 0; k < 4; k++)
                    h2[k] = __hfma2(h2[k], pw2[k], __hmul2(u2, b2a[k]));
                #pragma unroll
                for (int k = 0; k < 4; k++)
                    h2[4 + k] = __hfma2(h2[4 + k], pw2[4 + k], __hmul2(u2, b2b[k]));
            }
        }
        float pw[16];
        powers16(__expf(A0 * S), pw);
        #pragma unroll
        for (int k = 0; k < 8; k++) {
            float2 hf = __bfloat1622float2(h2[k]);
            hend[base + (size_t)(2 * k)     * D_MODEL] = hf.x;
            hend[base + (size_t)(2 * k + 1) * D_MODEL] = hf.y;
            Pp  [base + (size_t)(2 * k)     * D_MODEL] = pw[2 * k];
            Pp  [base + (size_t)(2 * k + 1) * D_MODEL] = pw[2 * k + 1];
        }
    } else {
        float h[D_STATE], P[D_STATE];
        #pragma unroll
        for (int n = 0; n < D_STATE; n++) { h[n] = 0.f; P[n] = 1.f; }
        const __nv_bfloat16* sBs = reinterpret_cast<const __nv_bfloat16*>(sB);
        for (int t = 0; t < TCH; t++) {
            float dtv = __bfloat162float(dtp[(size_t)t * D_MODEL]);
            float xv  = __bfloat162float(xp [(size_t)t * D_MODEL]);
            float u   = xv * dtv;
            #pragma unroll
            for (int n = 0; n < D_STATE; n++) {
                float pw = __expf(A[n] * dtv);
                h[n] = fmaf(h[n], pw, u * __bfloat162float(sBs[t * D_STATE + n]));
                P[n] *= pw;
            }
        }
        #pragma unroll
        for (int n = 0; n < D_STATE; n++) {
            hend[base + (size_t)n * D_MODEL] = h[n];
            Pp  [base + (size_t)n * D_MODEL] = P[n];
        }
    }
}

// pass 2: sequential combine over chunks -> chunk-entry states
__global__ void scan_combine(const float* __restrict__ hend, const float* __restrict__ Pp,
                             float* __restrict__ sin_)
{
    int idx = blockIdx.x * blockDim.x + threadIdx.x;
    if (idx >= B_SZ * D_STATE * D_MODEL) return;
    int d = idx % D_MODEL;
    int n = (idx / D_MODEL) % D_STATE;
    int b = idx / (D_MODEL * D_STATE);

    float s = 0.f;
    for (int ch = 0; ch < NCH; ch++) {
        size_t off = ((size_t)(b * NCH + ch) * D_STATE + n) * D_MODEL + d;
        sin_[off] = s;
        s = fmaf(Pp[off], s, hend[off]);
    }
}

// pass 3: replay chunks with correct entry state; emit y + residual
__global__ __launch_bounds__(256)
void scan_pass3(const __nv_bfloat16* __restrict__ dt, const __nv_bfloat16* __restrict__ pdec,
                const __nv_bfloat16* __restrict__ Bm, const __nv_bfloat16* __restrict__ Cm,
                const float* __restrict__ x, const float* __restrict__ A_log,
                const float* __restrict__ Dp, const float* __restrict__ sin_,
                float* __restrict__ y)
{
    __shared__ __align__(16) __nv_bfloat162 sB[TCH * 8];
    __shared__ __align__(16) __nv_bfloat162 sC[TCH * 8];
    int d  = blockIdx.x * blockDim.x + threadIdx.x;
    int ch = blockIdx.y;
    int b  = blockIdx.z;
    int t0 = ch * TCH;

    {
        const uint4* srcB = reinterpret_cast<const uint4*>(Bm + ((size_t)(b * T_SEQ + t0)) * D_STATE);
        const uint4* srcC = reinterpret_cast<const uint4*>(Cm + ((size_t)(b * T_SEQ + t0)) * D_STATE);
        uint4* dB = reinterpret_cast<uint4*>(sB);
        uint4* dC = reinterpret_cast<uint4*>(sC);
        for (int i = threadIdx.x; i < TCH * D_STATE / 8; i += blockDim.x) { dB[i] = srcB[i]; dC[i] = srcC[i]; }
    }
    __syncthreads();

    float A[D_STATE]; bool fast;
    load_A_and_mode(A_log, d, A, fast);

    size_t base = ((size_t)(b * NCH + ch) * D_STATE) * D_MODEL + d;
    float dpar = Dp[d];
    const __nv_bfloat16* dtp = dt   + ((size_t)(b * T_SEQ + t0)) * D_MODEL + d;
    const __nv_bfloat16* pp  = pdec + ((size_t)(b * T_SEQ + t0)) * D_MODEL + d;
    const float* xp          = x    + ((size_t)(b * T_SEQ + t0)) * D_MODEL + d;
    float* yp                = y    + ((size_t)(b * T_SEQ + t0)) * D_MODEL + d;

    if (fast) {
        __nv_bfloat162 h2[8];
        #pragma unroll
        for (int k = 0; k < 8; k++)
            h2[k] = __floats2bfloat162_rn(sin_[base + (size_t)(2 * k) * D_MODEL],
                                          sin_[base + (size_t)(2 * k + 1) * D_MODEL]);

        for (int t = 0; t < TCH; t += 4) {
            __nv_bfloat16 dtv[4], pv[4];
            float xv[4];
            #pragma unroll
            for (int j = 0; j < 4; j++) {
                dtv[j] = dtp[(size_t)(t + j) * D_MODEL];
                pv[j]  = pp [(size_t)(t + j) * D_MODEL];
                xv[j]  = xp [(size_t)(t + j) * D_MODEL];
            }
            float yv[4];
            #pragma unroll
            for (int j = 0; j < 4; j++) {
                float u = xv[j] * __bfloat162float(dtv[j]);
                __nv_bfloat162 pw2[8];
                powers16_h2b(pv[j], pw2);
                __nv_bfloat162 u2 = __float2bfloat162_rn(u);
                const uint4* browp = reinterpret_cast<const uint4*>(sB + (t + j) * 8);
                const uint4* crowp = reinterpret_cast<const uint4*>(sC + (t + j) * 8);
                uint4 br0 = browp[0], br1 = browp[1];
                uint4 cr0 = crowp[0], cr1 = crowp[1];
                const __nv_bfloat162* b2a = reinterpret_cast<const __nv_bfloat162*>(&br0);
                const __nv_bfloat162* b2b = reinterpret_cast<const __nv_bfloat162*>(&br1);
                const __nv_bfloat162* c2a = reinterpret_cast<const __nv_bfloat162*>(&cr0);
                const __nv_bfloat162* c2b = reinterpret_cast<const __nv_bfloat162*>(&cr1);
                __nv_bfloat162 acc2 = __floats2bfloat162_rn(0.f, 0.f);
                #pragma unroll
                for (int k = 0; k < 4; k++) {
                    h2[k] = __hfma2(h2[k], pw2[k], __hmul2(u2, b2a[k]));
                    acc2  = __hfma2(h2[k], c2a[k], acc2);
                }
                #pragma unroll
                for (int k = 0; k < 4; k++) {
                    h2[4 + k] = __hfma2(h2[4 + k], pw2[4 + k], __hmul2(u2, b2b[k]));
                    acc2      = __hfma2(h2[4 + k], c2b[k], acc2);
                }
                float2 af = __bfloat1622float2(acc2);
                yv[j] = fmaf(xv[j], dpar, af.x + af.y);
            }
            #pragma unroll
            for (int j = 0; j < 4; j++)
                yp[(size_t)(t + j) * D_MODEL] = yv[j];
        }
    } else {
        float h[D_STATE];
        #pragma unroll
        for (int n = 0; n < D_STATE; n++) h[n] = sin_[base + (size_t)n * D_MODEL];
        const __nv_bfloat16* sBs = reinterpret_cast<const __nv_bfloat16*>(sB);
        const __nv_bfloat16* sCs = reinterpret_cast<const __nv_bfloat16*>(sC);
        for (int t = 0; t < TCH; t++) {
            float dtv = __bfloat162float(dtp[(size_t)t * D_MODEL]);
            float xv  = xp [(size_t)t * D_MODEL];
            float u   = xv * dtv;
            float acc = 0.f;
            #pragma unroll
            for (int n = 0; n < D_STATE; n++) {
                float pw = __expf(A[n] * dtv);
                h[n] = fmaf(h[n], pw, u * __bfloat162float(sBs[t * D_STATE + n]));
                acc  = fmaf(h[n], __bfloat162float(sCs[t * D_STATE + n]), acc);
            }
            yp[(size_t)t * D_MODEL] = fmaf(xv, dpar, acc);
        }
    }
}

// ---------------- launch ------------------------------------------------------
extern "C" void kernel_launch(void* const* d_in, const int* in_sizes, int n_in,
                              void* d_out, int out_size)
{
    const float* x      = (const float*)d_in[0];
    const float* W_in   = (const float*)d_in[1];
    const float* conv_w = (const float*)d_in[2];
    const float* conv_b = (const float*)d_in[3];
    const float* W_dt   = (const float*)d_in[4];
    const float* b_dt   = (const float*)d_in[5];
    const float* A_log  = (const float*)d_in[6];
    const float* D_par  = (const float*)d_in[7];
    const float* W_B    = (const float*)d_in[8];
    const float* W_C    = (const float*)d_in[9];
    float* y = (float*)d_out;

    __nv_bfloat16 *xbf, *xssm_bf, *xconv_bf, *win_bf, *wcat_bf, *dtbf, *pbf, *Bmbf, *Cmbf;
    float *hend, *Pp, *sin_;
    cudaGetSymbolAddress((void**)&xbf,      g_xbf);
    cudaGetSymbolAddress((void**)&xssm_bf,  g_xssm_bf);
    cudaGetSymbolAddress((void**)&xconv_bf, g_xconv_bf);
    cudaGetSymbolAddress((void**)&win_bf,   g_Win_bf);
    cudaGetSymbolAddress((void**)&wcat_bf,  g_Wcat_bf);
    cudaGetSymbolAddress((void**)&dtbf,  g_dtbf);
    cudaGetSymbolAddress((void**)&pbf,   g_pbf);
    cudaGetSymbolAddress((void**)&Bmbf,  g_Bmbf);
    cudaGetSymbolAddress((void**)&Cmbf,  g_Cmbf);
    cudaGetSymbolAddress((void**)&hend,  g_hend);
    cudaGetSymbolAddress((void**)&Pp,    g_Pp);
    cudaGetSymbolAddress((void**)&sin_,  g_sin);

    cudaFuncSetAttribute(gemm_bf16, cudaFuncAttributeMaxDynamicSharedMemorySize, GEMM_SMEM);

    // 0) precision prep: x -> bf16; W_in[:768] -> bf16; [W_dt; W_B; W_C; 0] -> bf16
    int n4x = M_ROWS * D_MODEL / 4;
    cvt_f32_bf16<<<(n4x + 255) / 256, 256>>>(x, xbf, n4x);
    int n4w = D_MODEL * D_MODEL / 4;
    cvt_f32_bf16<<<(n4w + 255) / 256, 256>>>(W_in, win_bf, n4w);
    int n4c = NCAT * D_MODEL / 4;
    build_wcat<<<(n4c + 255) / 256, 256>>>(W_dt, W_B, W_C, wcat_bf);

    // 1) x_ssm = x @ W_in[:768].T  (z half is dead code); bf16 out
    dim3 g1(D_MODEL / 128, M_ROWS / 128);
    gemm_bf16<<<g1, 256, GEMM_SMEM>>>(xbf, win_bf, nullptr, xssm_bf,
                                      nullptr, nullptr, nullptr, nullptr, 0);

    // 2) depthwise causal conv + bias + SiLU (bf16 -> bf16)
    int pairs = M_ROWS * D_MODEL / 2;
    conv_silu_bf16<<<(pairs + 255) / 256, 256>>>(xssm_bf, conv_w, conv_b, xconv_bf);

    // 3) fused: dt (bf16) + p = exp(-dt) (bf16); Bm/Cm (bf16)
    dim3 g2(NCAT / 128, M_ROWS / 128);
    gemm_bf16<<<g2, 256, GEMM_SMEM>>>(xconv_bf, wcat_bf, b_dt, nullptr,
                                      dtbf, pbf, Bmbf, Cmbf, 1);

    // 4-6) chunked associative scan (bf16x2 packed states; zero per-step MUFU)
    dim3 scan_grid(D_MODEL / 256, NCH, B_SZ);
    scan_pass1<<<scan_grid, 256>>>(dtbf, pbf, Bmbf, xbf, A_log, hend, Pp);
    scan_combine<<<(B_SZ * D_STATE * D_MODEL + 255) / 256, 256>>>(hend, Pp, sin_);
    scan_pass3<<<scan_grid, 256>>>(dtbf, pbf, Bmbf, Cmbf, x, A_log, D_par, sin_, y);
}

// round 9
// speedup vs baseline: 1.2842x; 1.0208x over previous
#include <cuda_runtime.h>
#include <cuda_bf16.h>
#include <cstdint>

// Problem constants
#define B_SZ 8
#define T_SEQ 2048
#define D_MODEL 768
#define D_STATE 16
#define D_CONV 4
#define M_ROWS (B_SZ * T_SEQ)          // 16384
#define NCH 32                          // scan chunks
#define TCH (T_SEQ / NCH)               // 64 steps per chunk
#define NCAT 896                        // padded fused-GEMM2 N (768 dt + 16 B + 16 C + 96 pad)

// ---------------- scratch (__device__ globals; no runtime alloc) -------------
__device__ __nv_bfloat16 g_xbf     [M_ROWS * D_MODEL];
__device__ __nv_bfloat16 g_xssm_bf [M_ROWS * D_MODEL];
__device__ __nv_bfloat16 g_xconv_bf[M_ROWS * D_MODEL];
__device__ __nv_bfloat16 g_Win_bf  [D_MODEL * D_MODEL];
__device__ __nv_bfloat16 g_Wcat_bf [NCAT * D_MODEL];
__device__ uint32_t g_dp [M_ROWS * D_MODEL];   // packed (dt, p) bf16x2
__device__ __nv_bfloat16 g_Bmbf [M_ROWS * D_STATE];
__device__ __nv_bfloat16 g_Cmbf [M_ROWS * D_STATE];
__device__ float g_hend [B_SZ * NCH * D_STATE * D_MODEL];
__device__ float g_Pp   [B_SZ * NCH * D_STATE * D_MODEL];
__device__ float g_sin  [B_SZ * NCH * D_STATE * D_MODEL];

// ============================ PTX helpers =====================================
__device__ __forceinline__ uint32_t smem_u32(const void* p) {
    uint32_t a;
    asm("{ .reg .u64 t; cvta.to.shared.u64 t, %1; cvt.u32.u64 %0, t; }" : "=r"(a) : "l"(p));
    return a;
}
__device__ __forceinline__ void ldsm_x4(uint32_t addr, uint32_t& r0, uint32_t& r1,
                                        uint32_t& r2, uint32_t& r3) {
    asm volatile("ldmatrix.sync.aligned.m8n8.x4.shared.b16 {%0,%1,%2,%3}, [%4];"
                 : "=r"(r0), "=r"(r1), "=r"(r2), "=r"(r3) : "r"(addr));
}
__device__ __forceinline__ void mma_bf16(float* c,
                                         uint32_t a0, uint32_t a1, uint32_t a2, uint32_t a3,
                                         uint32_t b0, uint32_t b1) {
    asm volatile("mma.sync.aligned.m16n8k16.row.col.f32.bf16.bf16.f32 "
                 "{%0,%1,%2,%3}, {%4,%5,%6,%7}, {%8,%9}, {%0,%1,%2,%3};"
                 : "+f"(c[0]), "+f"(c[1]), "+f"(c[2]), "+f"(c[3])
                 : "r"(a0), "r"(a1), "r"(a2), "r"(a3), "r"(b0), "r"(b1));
}
__device__ __forceinline__ __nv_bfloat16 f2bf(float x) { return __float2bfloat16_rn(x); }

#define CP16(dst, src) \
    asm volatile("cp.async.cg.shared.global [%0], [%1], 16;" :: "r"(dst), "l"(src) : "memory")
#define CP_COMMIT()  asm volatile("cp.async.commit_group;" ::: "memory")
#define CP_WAIT1()   asm volatile("cp.async.wait_group 1;" ::: "memory")

// ===================== bf16 mma.sync GEMM (round-5 validated config) ==========
// C[M, N] = A[M, 768](bf16) * W[N, 768](bf16)^T, fp32 accumulate.
// tile 128x128, BK=32, 3-stage cp.async pipeline (dynamic smem). 8 warps, 64x32 each.
// mode 0: write bf16 to outBF (no act).
// mode 1: fused epilogue: cols <768 -> w = v + bias; dt = softplus(w), p = 1/(1+e^w)
//         packed as bf16x2 into outDP; cols 768..783 -> Bm; 784..799 -> Cm; >=800 off.
#define GK 768
#define CHKB 32
#define NKB (GK / CHKB)                 // 24
#define SRB 40                          // 32 + 8 pad bf16 (80B row; LDSM conflict-free)
#define ROWB (SRB * 2)                  // 80 bytes per smem row
#define MATB (128 * ROWB)               // 10240 bytes per matrix per stage
#define STGB (2 * MATB)                 // 20480 bytes per stage (A + W)
#define GEMM_SMEM (3 * STGB)            // 61440

__global__ __launch_bounds__(256, 2)
void gemm_bf16(const __nv_bfloat16* __restrict__ A, const __nv_bfloat16* __restrict__ W,
               const float* __restrict__ bias, __nv_bfloat16* __restrict__ outBF,
               uint32_t* __restrict__ outDP,
               __nv_bfloat16* __restrict__ Bm, __nv_bfloat16* __restrict__ Cm, int mode)
{
    extern __shared__ __align__(16) char smem_raw[];
    const uint32_t sbase = smem_u32(smem_raw);

    const int tid  = threadIdx.x;
    const int wid  = tid >> 5;
    const int lane = tid & 31;
    const int bn   = blockIdx.x * 128;
    const int bm   = blockIdx.y * 128;
    const int wm   = (wid & 1) * 64;
    const int wn   = (wid >> 1) * 32;

    float acc[4][4][4];
    #pragma unroll
    for (int i = 0; i < 4; i++)
        #pragma unroll
        for (int j = 0; j < 4; j++)
            #pragma unroll
            for (int c = 0; c < 4; c++) acc[i][j][c] = 0.f;

    // cp.async pattern: per chunk per matrix 128 rows x 64B = 512 x 16B; 2/thread/matrix
    const int r0 = tid >> 2;              // 0..63
    const int c8 = (tid & 3) * 8;         // bf16 elem offset 0,8,16,24
    const __nv_bfloat16* Aptr = A + (size_t)(bm + r0) * GK + c8;
    const __nv_bfloat16* Wptr = W + (size_t)(bn + r0) * GK + c8;
    const size_t gstep = (size_t)64 * GK;

    const uint32_t dA0 = sbase + (uint32_t)(r0 * ROWB + c8 * 2);
    const uint32_t dW0 = dA0 + MATB;

    auto issue = [&](int k) {
        uint32_t off = (uint32_t)(k % 3) * STGB;
        const __nv_bfloat16* a0 = Aptr + (size_t)k * CHKB;
        const __nv_bfloat16* w0 = Wptr + (size_t)k * CHKB;
        CP16(dA0 + off,                 a0);
        CP16(dA0 + off + 64u * ROWB,    a0 + gstep);
        CP16(dW0 + off,                 w0);
        CP16(dW0 + off + 64u * ROWB,    w0 + gstep);
        CP_COMMIT();
    };

    // ldmatrix lane addressing (validated round 4)
    const int arow = lane & 15;                       // A: rows m0..15
    const int ak   = (lane >> 4) * 8;                 // A: k half
    const int brow = ((lane >> 4) * 8) + (lane & 7);  // B: n row within 16
    const int bk   = ((lane >> 3) & 1) * 8;           // B: k half

    const uint32_t aAddr0 = sbase + (uint32_t)((wm + arow) * ROWB + ak * 2);
    const uint32_t bAddr0 = sbase + MATB + (uint32_t)((wn + brow) * ROWB + bk * 2);

    issue(0);
    issue(1);

    for (int k = 0; k < NKB; k++) {
        CP_WAIT1();
        __syncthreads();
        if (k + 2 < NKB) issue(k + 2);

        const uint32_t off = (uint32_t)(k % 3) * STGB;
        #pragma unroll
        for (int ks = 0; ks < 2; ks++) {
            const uint32_t koff = off + (uint32_t)(ks * 32);   // 16 bf16 = 32 bytes
            uint32_t bf[4][2];
            ldsm_x4(bAddr0 + koff,               bf[0][0], bf[0][1], bf[1][0], bf[1][1]);
            ldsm_x4(bAddr0 + koff + 16u * ROWB,  bf[2][0], bf[2][1], bf[3][0], bf[3][1]);
            #pragma unroll
            for (int mf = 0; mf < 4; mf++) {
                uint32_t a0, a1, a2, a3;
                ldsm_x4(aAddr0 + koff + (uint32_t)(mf * 16 * ROWB), a0, a1, a2, a3);
                #pragma unroll
                for (int nf = 0; nf < 4; nf++)
                    mma_bf16(acc[mf][nf], a0, a1, a2, a3, bf[nf][0], bf[nf][1]);
            }
        }
    }

    // epilogue: c0/c1 = (row, col/col+1); c2/c3 = row+8
    const int erow = lane >> 2;
    const int ecol = (lane & 3) * 2;
    #pragma unroll
    for (int mf = 0; mf < 4; mf++) {
        int row = bm + wm + mf * 16 + erow;
        #pragma unroll
        for (int nf = 0; nf < 4; nf++) {
            int col = bn + wn + nf * 8 + ecol;
            float v0 = acc[mf][nf][0], v1 = acc[mf][nf][1];
            float v2 = acc[mf][nf][2], v3 = acc[mf][nf][3];
            if (mode == 0) {
                __nv_bfloat162 p0 = { f2bf(v0), f2bf(v1) };
                __nv_bfloat162 p1 = { f2bf(v2), f2bf(v3) };
                *reinterpret_cast<__nv_bfloat162*>(outBF + (size_t)row * D_MODEL + col)       = p0;
                *reinterpret_cast<__nv_bfloat162*>(outBF + (size_t)(row + 8) * D_MODEL + col) = p1;
            } else if (col < 768) {
                float b0 = bias[col], b1 = bias[col + 1];
                float w0 = v0 + b0, w1 = v1 + b1, w2 = v2 + b0, w3 = v3 + b1;
                float e0 = __expf(w0), e1 = __expf(w1), e2 = __expf(w2), e3 = __expf(w3);
                float dt0 = (w0 > 20.f) ? w0 : log1pf(e0);
                float dt1 = (w1 > 20.f) ? w1 : log1pf(e1);
                float dt2 = (w2 > 20.f) ? w2 : log1pf(e2);
                float dt3 = (w3 > 20.f) ? w3 : log1pf(e3);
                float q0 = __fdividef(1.f, 1.f + e0);
                float q1 = __fdividef(1.f, 1.f + e1);
                float q2 = __fdividef(1.f, 1.f + e2);
                float q3 = __fdividef(1.f, 1.f + e3);
                // packed (dt, p) pairs
                __nv_bfloat162 dp0 = { f2bf(dt0), f2bf(q0) };
                __nv_bfloat162 dp1 = { f2bf(dt1), f2bf(q1) };
                __nv_bfloat162 dp2 = { f2bf(dt2), f2bf(q2) };
                __nv_bfloat162 dp3 = { f2bf(dt3), f2bf(q3) };
                uint2 lo = { *reinterpret_cast<uint32_t*>(&dp0), *reinterpret_cast<uint32_t*>(&dp1) };
                uint2 hi = { *reinterpret_cast<uint32_t*>(&dp2), *reinterpret_cast<uint32_t*>(&dp3) };
                *reinterpret_cast<uint2*>(outDP + (size_t)row * D_MODEL + col)       = lo;
                *reinterpret_cast<uint2*>(outDP + (size_t)(row + 8) * D_MODEL + col) = hi;
            } else if (col < 784) {
                int n = col - 768;
                __nv_bfloat162 p0 = { f2bf(v0), f2bf(v1) };
                __nv_bfloat162 p1 = { f2bf(v2), f2bf(v3) };
                *reinterpret_cast<__nv_bfloat162*>(Bm + (size_t)row * D_STATE + n)       = p0;
                *reinterpret_cast<__nv_bfloat162*>(Bm + (size_t)(row + 8) * D_STATE + n) = p1;
            } else if (col < 800) {
                int n = col - 784;
                __nv_bfloat162 p0 = { f2bf(v0), f2bf(v1) };
                __nv_bfloat162 p1 = { f2bf(v2), f2bf(v3) };
                *reinterpret_cast<__nv_bfloat162*>(Cm + (size_t)row * D_STATE + n)       = p0;
                *reinterpret_cast<__nv_bfloat162*>(Cm + (size_t)(row + 8) * D_STATE + n) = p1;
            }
        }
    }
}

// ---------------- fp32 -> bf16 bulk convert ----------------------------------
__global__ void cvt_f32_bf16(const float* __restrict__ in, __nv_bfloat16* __restrict__ out, int n4)
{
    int idx = blockIdx.x * blockDim.x + threadIdx.x;
    if (idx >= n4) return;
    float4 v = reinterpret_cast<const float4*>(in)[idx];
    __nv_bfloat162 lo = { f2bf(v.x), f2bf(v.y) };
    __nv_bfloat162 hi = { f2bf(v.z), f2bf(v.w) };
    uint2 u = { *reinterpret_cast<uint32_t*>(&lo), *reinterpret_cast<uint32_t*>(&hi) };
    reinterpret_cast<uint2*>(out)[idx] = u;
}

// ---------------- build concatenated weight (bf16) ---------------------------
__global__ void build_wcat(const float* __restrict__ W_dt, const float* __restrict__ W_B,
                           const float* __restrict__ W_C, __nv_bfloat16* __restrict__ out)
{
    int idx = blockIdx.x * blockDim.x + threadIdx.x;
    if (idx >= NCAT * D_MODEL / 4) return;
    int r  = idx / (D_MODEL / 4);
    int c4 = (idx % (D_MODEL / 4)) * 4;
    float4 v = make_float4(0.f, 0.f, 0.f, 0.f);
    if (r < 768)      v = *reinterpret_cast<const float4*>(W_dt + (size_t)r * D_MODEL + c4);
    else if (r < 784) v = *reinterpret_cast<const float4*>(W_B + (size_t)(r - 768) * D_MODEL + c4);
    else if (r < 800) v = *reinterpret_cast<const float4*>(W_C + (size_t)(r - 784) * D_MODEL + c4);
    __nv_bfloat162 lo = { f2bf(v.x), f2bf(v.y) };
    __nv_bfloat162 hi = { f2bf(v.z), f2bf(v.w) };
    uint2 u = { *reinterpret_cast<uint32_t*>(&lo), *reinterpret_cast<uint32_t*>(&hi) };
    reinterpret_cast<uint2*>(out)[idx] = u;
}

// ---------------- depthwise causal conv (K=4) + bias + SiLU, bf16 in/out -----
__global__ void conv_silu_bf16(const __nv_bfloat16* __restrict__ xin,
                               const float* __restrict__ cw,
                               const float* __restrict__ cb,
                               __nv_bfloat16* __restrict__ out)
{
    int idx = blockIdx.x * blockDim.x + threadIdx.x;   // pair index
    if (idx >= M_ROWS * D_MODEL / 2) return;
    int d2 = idx % (D_MODEL / 2);
    int t  = (idx / (D_MODEL / 2)) % T_SEQ;
    int d  = d2 * 2;

    float a0 = cb[d], a1 = cb[d + 1];
    #pragma unroll
    for (int k = 0; k < D_CONV; k++) {
        int rel = k - (D_CONV - 1);
        if (t + rel >= 0) {
            __nv_bfloat162 xv = reinterpret_cast<const __nv_bfloat162*>(xin)[idx + rel * (D_MODEL / 2)];
            float f0 = __bfloat162float(xv.x), f1 = __bfloat162float(xv.y);
            a0 = fmaf(f0, cw[d * D_CONV + k], a0);
            a1 = fmaf(f1, cw[(d + 1) * D_CONV + k], a1);
        }
    }
    float s0 = a0 / (1.f + __expf(-a0));
    float s1 = a1 / (1.f + __expf(-a1));
    __nv_bfloat162 o = { f2bf(s0), f2bf(s1) };
    reinterpret_cast<__nv_bfloat162*>(out)[idx] = o;
}

// ---------------- scan helpers ------------------------------------------------
__device__ __forceinline__ void load_A_and_mode(const float* __restrict__ A_log,
                                                int d, float* A, bool& fast)
{
    #pragma unroll
    for (int n = 0; n < D_STATE; n++) A[n] = -__expf(A_log[d * D_STATE + n]);
    fast = true;
    // fast path requires A[n] = (n+1) * A0 AND A0 == -1 (p = exp(-dt) precomputed)
    fast = fast && (fabsf(A[0] + 1.f) <= 1e-5f);
    #pragma unroll
    for (int n = 1; n < D_STATE; n++)
        fast = fast && (fabsf(A[n] - (float)(n + 1) * A[0]) <= 1e-4f * fabsf(A[n]));
}

// scalar powers: pw[n] = p^(n+1)
__device__ __forceinline__ void powers16(float p1, float* pw)
{
    float p2 = p1 * p1, p4 = p2 * p2, p8 = p4 * p4;
    pw[0] = p1;        pw[1] = p2;        pw[2] = p2 * p1;   pw[3] = p4;
    pw[4] = p4 * p1;   pw[5] = p4 * p2;   pw[6] = p4 * pw[2]; pw[7] = p8;
    pw[8] = p8 * p1;   pw[9] = p8 * p2;   pw[10] = p8 * pw[2]; pw[11] = p8 * p4;
    pw[12] = p8 * pw[4]; pw[13] = p8 * pw[5]; pw[14] = p8 * pw[6]; pw[15] = p8 * p8;
}

// packed bf16x2 powers from bf16 base: pw2[k] = (p^(2k+1), p^(2k+2))
__device__ __forceinline__ void powers16_h2b(__nv_bfloat16 p, __nv_bfloat162* pw2)
{
    __nv_bfloat16 psq = __hmul(p, p);
    __nv_bfloat162 st = { psq, psq };
    pw2[0].x = p; pw2[0].y = psq;
    #pragma unroll
    for (int k = 1; k < 8; k++) pw2[k] = __hmul2(pw2[k - 1], st);
}

// pass 1: per-chunk local scan from h=0; emit end-state and cumulative decay
__global__ __launch_bounds__(256)
void scan_pass1(const uint32_t* __restrict__ dp, const __nv_bfloat16* __restrict__ Bm,
                const __nv_bfloat16* __restrict__ x, const float* __restrict__ A_log,
                float* __restrict__ hend, float* __restrict__ Pp)
{
    __shared__ __align__(16) __nv_bfloat162 sB[TCH * 8];
    int d  = blockIdx.x * blockDim.x + threadIdx.x;
    int ch = blockIdx.y;
    int b  = blockIdx.z;
    int t0 = ch * TCH;

    {
        const uint4* src = reinterpret_cast<const uint4*>(Bm + ((size_t)(b * T_SEQ + t0)) * D_STATE);
        uint4* dst = reinterpret_cast<uint4*>(sB);
        for (int i = threadIdx.x; i < TCH * D_STATE / 8; i += blockDim.x) dst[i] = src[i];
    }
    __syncthreads();

    float A[D_STATE]; bool fast;
    load_A_and_mode(A_log, d, A, fast);

    const uint32_t* dpp     = dp + ((size_t)(b * T_SEQ + t0)) * D_MODEL + d;
    const __nv_bfloat16* xp = x  + ((size_t)(b * T_SEQ + t0)) * D_MODEL + d;
    size_t base = ((size_t)(b * NCH + ch) * D_STATE) * D_MODEL + d;

    if (fast) {
        const float A0 = A[0];
        __nv_bfloat162 h2[8];
        #pragma unroll
        for (int k = 0; k < 8; k++) h2[k] = __floats2bfloat162_rn(0.f, 0.f);
        float S = 0.f;

        uint32_t cur_dp[4]; __nv_bfloat16 cur_x[4];
        #pragma unroll
        for (int j = 0; j < 4; j++) {
            cur_dp[j] = dpp[(size_t)j * D_MODEL];
            cur_x[j]  = xp [(size_t)j * D_MODEL];
        }
        for (int t = 0; t < TCH; t += 4) {
            uint32_t nxt_dp[4]; __nv_bfloat16 nxt_x[4];
            if (t + 4 < TCH) {
                #pragma unroll
                for (int j = 0; j < 4; j++) {
                    nxt_dp[j] = dpp[(size_t)(t + 4 + j) * D_MODEL];
                    nxt_x[j]  = xp [(size_t)(t + 4 + j) * D_MODEL];
                }
            }
            #pragma unroll
            for (int j = 0; j < 4; j++) {
                __nv_bfloat162 dpv = *reinterpret_cast<__nv_bfloat162*>(&cur_dp[j]);
                float dtf = __bfloat162float(dpv.x);
                float u   = __bfloat162float(cur_x[j]) * dtf;
                S += dtf;
                __nv_bfloat162 pw2[8];
                powers16_h2b(dpv.y, pw2);
                __nv_bfloat162 u2 = __float2bfloat162_rn(u);
                const uint4* brow = reinterpret_cast<const uint4*>(sB + (t + j) * 8);
                uint4 br0 = brow[0], br1 = brow[1];
                const __nv_bfloat162* b2a = reinterpret_cast<const __nv_bfloat162*>(&br0);
                const __nv_bfloat162* b2b = reinterpret_cast<const __nv_bfloat162*>(&br1);
                #pragma unroll
                for (int k = 0; k < 4; k++)
                    h2[k] = __hfma2(h2[k], pw2[k], __hmul2(u2, b2a[k]));
                #pragma unroll
                for (int k = 0; k < 4; k++)
                    h2[4 + k] = __hfma2(h2[4 + k], pw2[4 + k], __hmul2(u2, b2b[k]));
            }
            #pragma unroll
            for (int j = 0; j < 4; j++) { cur_dp[j] = nxt_dp[j]; cur_x[j] = nxt_x[j]; }
        }
        float pw[16];
        powers16(__expf(A0 * S), pw);
        #pragma unroll
        for (int k = 0; k < 8; k++) {
            float2 hf = __bfloat1622float2(h2[k]);
            hend[base + (size_t)(2 * k)     * D_MODEL] = hf.x;
            hend[base + (size_t)(2 * k + 1) * D_MODEL] = hf.y;
            Pp  [base + (size_t)(2 * k)     * D_MODEL] = pw[2 * k];
            Pp  [base + (size_t)(2 * k + 1) * D_MODEL] = pw[2 * k + 1];
        }
    } else {
        float h[D_STATE], P[D_STATE];
        #pragma unroll
        for (int n = 0; n < D_STATE; n++) { h[n] = 0.f; P[n] = 1.f; }
        const __nv_bfloat16* sBs = reinterpret_cast<const __nv_bfloat16*>(sB);
        for (int t = 0; t < TCH; t++) {
            uint32_t dpw = dpp[(size_t)t * D_MODEL];
            __nv_bfloat162 dpv = *reinterpret_cast<__nv_bfloat162*>(&dpw);
            float dtv = __bfloat162float(dpv.x);
            float xv  = __bfloat162float(xp[(size_t)t * D_MODEL]);
            float u   = xv * dtv;
            #pragma unroll
            for (int n = 0; n < D_STATE; n++) {
                float pw = __expf(A[n] * dtv);
                h[n] = fmaf(h[n], pw, u * __bfloat162float(sBs[t * D_STATE + n]));
                P[n] *= pw;
            }
        }
        #pragma unroll
        for (int n = 0; n < D_STATE; n++) {
            hend[base + (size_t)n * D_MODEL] = h[n];
            Pp  [base + (size_t)n * D_MODEL] = P[n];
        }
    }
}

// pass 2: sequential combine over chunks -> chunk-entry states
__global__ void scan_combine(const float* __restrict__ hend, const float* __restrict__ Pp,
                             float* __restrict__ sin_)
{
    int idx = blockIdx.x * blockDim.x + threadIdx.x;
    if (idx >= B_SZ * D_STATE * D_MODEL) return;
    int d = idx % D_MODEL;
    int n = (idx / D_MODEL) % D_STATE;
    int b = idx / (D_MODEL * D_STATE);

    float s = 0.f;
    for (int ch = 0; ch < NCH; ch++) {
        size_t off = ((size_t)(b * NCH + ch) * D_STATE + n) * D_MODEL + d;
        sin_[off] = s;
        s = fmaf(Pp[off], s, hend[off]);
    }
}

// pass 3: replay chunks with correct entry state; emit y + residual
__global__ __launch_bounds__(256)
void scan_pass3(const uint32_t* __restrict__ dp, const __nv_bfloat16* __restrict__ Bm,
                const __nv_bfloat16* __restrict__ Cm, const float* __restrict__ x,
                const float* __restrict__ A_log, const float* __restrict__ Dp,
                const float* __restrict__ sin_, float* __restrict__ y)
{
    __shared__ __align__(16) __nv_bfloat162 sB[TCH * 8];
    __shared__ __align__(16) __nv_bfloat162 sC[TCH * 8];
    int d  = blockIdx.x * blockDim.x + threadIdx.x;
    int ch = blockIdx.y;
    int b  = blockIdx.z;
    int t0 = ch * TCH;

    {
        const uint4* srcB = reinterpret_cast<const uint4*>(Bm + ((size_t)(b * T_SEQ + t0)) * D_STATE);
        const uint4* srcC = reinterpret_cast<const uint4*>(Cm + ((size_t)(b * T_SEQ + t0)) * D_STATE);
        uint4* dB = reinterpret_cast<uint4*>(sB);
        uint4* dC = reinterpret_cast<uint4*>(sC);
        for (int i = threadIdx.x; i < TCH * D_STATE / 8; i += blockDim.x) { dB[i] = srcB[i]; dC[i] = srcC[i]; }
    }
    __syncthreads();

    float A[D_STATE]; bool fast;
    load_A_and_mode(A_log, d, A, fast);

    size_t base = ((size_t)(b * NCH + ch) * D_STATE) * D_MODEL + d;
    float dpar = Dp[d];
    const uint32_t* dpp = dp + ((size_t)(b * T_SEQ + t0)) * D_MODEL + d;
    const float* xp     = x  + ((size_t)(b * T_SEQ + t0)) * D_MODEL + d;
    float* yp           = y  + ((size_t)(b * T_SEQ + t0)) * D_MODEL + d;

    if (fast) {
        __nv_bfloat162 h2[8];
        #pragma unroll
        for (int k = 0; k < 8; k++)
            h2[k] = __floats2bfloat162_rn(sin_[base + (size_t)(2 * k) * D_MODEL],
                                          sin_[base + (size_t)(2 * k + 1) * D_MODEL]);

        uint32_t cur_dp[4]; float cur_x[4];
        #pragma unroll
        for (int j = 0; j < 4; j++) {
            cur_dp[j] = dpp[(size_t)j * D_MODEL];
            cur_x[j]  = xp [(size_t)j * D_MODEL];
        }
        for (int t = 0; t < TCH; t += 4) {
            uint32_t nxt_dp[4]; float nxt_x[4];
            if (t + 4 < TCH) {
                #pragma unroll
                for (int j = 0; j < 4; j++) {
                    nxt_dp[j] = dpp[(size_t)(t + 4 + j) * D_MODEL];
                    nxt_x[j]  = xp [(size_t)(t + 4 + j) * D_MODEL];
                }
            }
            float yv[4];
            #pragma unroll
            for (int j = 0; j < 4; j++) {
                __nv_bfloat162 dpv = *reinterpret_cast<__nv_bfloat162*>(&cur_dp[j]);
                float u = cur_x[j] * __bfloat162float(dpv.x);
                __nv_bfloat162 pw2[8];
                powers16_h2b(dpv.y, pw2);
                __nv_bfloat162 u2 = __float2bfloat162_rn(u);
                const uint4* browp = reinterpret_cast<const uint4*>(sB + (t + j) * 8);
                const uint4* crowp = reinterpret_cast<const uint4*>(sC + (t + j) * 8);
                uint4 br0 = browp[0], br1 = browp[1];
                uint4 cr0 = crowp[0], cr1 = crowp[1];
                const __nv_bfloat162* b2a = reinterpret_cast<const __nv_bfloat162*>(&br0);
                const __nv_bfloat162* b2b = reinterpret_cast<const __nv_bfloat162*>(&br1);
                const __nv_bfloat162* c2a = reinterpret_cast<const __nv_bfloat162*>(&cr0);
                const __nv_bfloat162* c2b = reinterpret_cast<const __nv_bfloat162*>(&cr1);
                __nv_bfloat162 acc2 = __floats2bfloat162_rn(0.f, 0.f);
                #pragma unroll
                for (int k = 0; k < 4; k++) {
                    h2[k] = __hfma2(h2[k], pw2[k], __hmul2(u2, b2a[k]));
                    acc2  = __hfma2(h2[k], c2a[k], acc2);
                }
                #pragma unroll
                for (int k = 0; k < 4; k++) {
                    h2[4 + k] = __hfma2(h2[4 + k], pw2[4 + k], __hmul2(u2, b2b[k]));
                    acc2      = __hfma2(h2[4 + k], c2b[k], acc2);
                }
                float2 af = __bfloat1622float2(acc2);
                yv[j] = fmaf(cur_x[j], dpar, af.x + af.y);
            }
            #pragma unroll
            for (int j = 0; j < 4; j++)
                yp[(size_t)(t + j) * D_MODEL] = yv[j];
            #pragma unroll
            for (int j = 0; j < 4; j++) { cur_dp[j] = nxt_dp[j]; cur_x[j] = nxt_x[j]; }
        }
    } else {
        float h[D_STATE];
        #pragma unroll
        for (int n = 0; n < D_STATE; n++) h[n] = sin_[base + (size_t)n * D_MODEL];
        const __nv_bfloat16* sBs = reinterpret_cast<const __nv_bfloat16*>(sB);
        const __nv_bfloat16* sCs = reinterpret_cast<const __nv_bfloat16*>(sC);
        for (int t = 0; t < TCH; t++) {
            uint32_t dpw = dpp[(size_t)t * D_MODEL];
            __nv_bfloat162 dpv = *reinterpret_cast<__nv_bfloat162*>(&dpw);
            float dtv = __bfloat162float(dpv.x);
            float xv  = xp [(size_t)t * D_MODEL];
            float u   = xv * dtv;
            float acc = 0.f;
            #pragma unroll
            for (int n = 0; n < D_STATE; n++) {
                float pw = __expf(A[n] * dtv);
                h[n] = fmaf(h[n], pw, u * __bfloat162float(sBs[t * D_STATE + n]));
                acc  = fmaf(h[n], __bfloat162float(sCs[t * D_STATE + n]), acc);
            }
            yp[(size_t)t * D_MODEL] = fmaf(xv, dpar, acc);
        }
    }
}

// ---------------- launch ------------------------------------------------------
extern "C" void kernel_launch(void* const* d_in, const int* in_sizes, int n_in,
                              void* d_out, int out_size)
{
    const float* x      = (const float*)d_in[0];
    const float* W_in   = (const float*)d_in[1];
    const float* conv_w = (const float*)d_in[2];
    const float* conv_b = (const float*)d_in[3];
    const float* W_dt   = (const float*)d_in[4];
    const float* b_dt   = (const float*)d_in[5];
    const float* A_log  = (const float*)d_in[6];
    const float* D_par  = (const float*)d_in[7];
    const float* W_B    = (const float*)d_in[8];
    const float* W_C    = (const float*)d_in[9];
    float* y = (float*)d_out;

    __nv_bfloat16 *xbf, *xssm_bf, *xconv_bf, *win_bf, *wcat_bf, *Bmbf, *Cmbf;
    uint32_t* dpb;
    float *hend, *Pp, *sin_;
    cudaGetSymbolAddress((void**)&xbf,      g_xbf);
    cudaGetSymbolAddress((void**)&xssm_bf,  g_xssm_bf);
    cudaGetSymbolAddress((void**)&xconv_bf, g_xconv_bf);
    cudaGetSymbolAddress((void**)&win_bf,   g_Win_bf);
    cudaGetSymbolAddress((void**)&wcat_bf,  g_Wcat_bf);
    cudaGetSymbolAddress((void**)&dpb,   g_dp);
    cudaGetSymbolAddress((void**)&Bmbf,  g_Bmbf);
    cudaGetSymbolAddress((void**)&Cmbf,  g_Cmbf);
    cudaGetSymbolAddress((void**)&hend,  g_hend);
    cudaGetSymbolAddress((void**)&Pp,    g_Pp);
    cudaGetSymbolAddress((void**)&sin_,  g_sin);

    cudaFuncSetAttribute(gemm_bf16, cudaFuncAttributeMaxDynamicSharedMemorySize, GEMM_SMEM);

    // 0) precision prep: x -> bf16; W_in[:768] -> bf16; [W_dt; W_B; W_C; 0] -> bf16
    int n4x = M_ROWS * D_MODEL / 4;
    cvt_f32_bf16<<<(n4x + 255) / 256, 256>>>(x, xbf, n4x);
    int n4w = D_MODEL * D_MODEL / 4;
    cvt_f32_bf16<<<(n4w + 255) / 256, 256>>>(W_in, win_bf, n4w);
    int n4c = NCAT * D_MODEL / 4;
    build_wcat<<<(n4c + 255) / 256, 256>>>(W_dt, W_B, W_C, wcat_bf);

    // 1) x_ssm = x @ W_in[:768].T  (z half is dead code); bf16 out
    dim3 g1(D_MODEL / 128, M_ROWS / 128);
    gemm_bf16<<<g1, 256, GEMM_SMEM>>>(xbf, win_bf, nullptr, xssm_bf,
                                      nullptr, nullptr, nullptr, 0);

    // 2) depthwise causal conv + bias + SiLU (bf16 -> bf16)
    int pairs = M_ROWS * D_MODEL / 2;
    conv_silu_bf16<<<(pairs + 255) / 256, 256>>>(xssm_bf, conv_w, conv_b, xconv_bf);

    // 3) fused: packed (dt, p = exp(-dt)) bf16x2; Bm/Cm (bf16)
    dim3 g2(NCAT / 128, M_ROWS / 128);
    gemm_bf16<<<g2, 256, GEMM_SMEM>>>(xconv_bf, wcat_bf, b_dt, nullptr,
                                      dpb, Bmbf, Cmbf, 1);

    // 4-6) chunked associative scan (32 chunks; prefetched, packed streams)
    dim3 scan_grid(D_MODEL / 256, NCH, B_SZ);
    scan_pass1<<<scan_grid, 256>>>(dpb, Bmbf, xbf, A_log, hend, Pp);
    scan_combine<<<(B_SZ * D_STATE * D_MODEL + 255) / 256, 256>>>(hend, Pp, sin_);
    scan_pass3<<<scan_grid, 256>>>(dpb, Bmbf, Cmbf, x, A_log, D_par, sin_, y);
}

// round 10
// speedup vs baseline: 1.2900x; 1.0045x over previous
#include <cuda_runtime.h>
#include <cuda_bf16.h>
#include <cstdint>

// Problem constants
#define B_SZ 8
#define T_SEQ 2048
#define D_MODEL 768
#define D_STATE 16
#define D_CONV 4
#define M_ROWS (B_SZ * T_SEQ)          // 16384
#define NCH 32                          // scan chunks
#define TCH (T_SEQ / NCH)               // 64 steps per chunk
#define NCAT 896                        // padded fused-GEMM2 N (768 dt + 16 B + 16 C + 96 pad)

// ---------------- scratch (__device__ globals; no runtime alloc) -------------
__device__ __nv_bfloat16 g_xbf     [M_ROWS * D_MODEL];
__device__ __nv_bfloat16 g_xssm_bf [M_ROWS * D_MODEL];
__device__ __nv_bfloat16 g_xconv_bf[M_ROWS * D_MODEL];
__device__ __nv_bfloat16 g_Win_bf  [D_MODEL * D_MODEL];
__device__ __nv_bfloat16 g_Wcat_bf [NCAT * D_MODEL];
__device__ uint32_t g_dp [M_ROWS * D_MODEL];   // packed (dt, p) bf16x2
__device__ __nv_bfloat16 g_Bmbf [M_ROWS * D_STATE];
__device__ __nv_bfloat16 g_Cmbf [M_ROWS * D_STATE];
__device__ float g_hend [B_SZ * NCH * D_STATE * D_MODEL];
__device__ float g_Pp   [B_SZ * NCH * D_STATE * D_MODEL];
__device__ float g_sin  [B_SZ * NCH * D_STATE * D_MODEL];

// ============================ PTX helpers =====================================
__device__ __forceinline__ uint32_t smem_u32(const void* p) {
    uint32_t a;
    asm("{ .reg .u64 t; cvta.to.shared.u64 t, %1; cvt.u32.u64 %0, t; }" : "=r"(a) : "l"(p));
    return a;
}
__device__ __forceinline__ void ldsm_x4(uint32_t addr, uint32_t& r0, uint32_t& r1,
                                        uint32_t& r2, uint32_t& r3) {
    asm volatile("ldmatrix.sync.aligned.m8n8.x4.shared.b16 {%0,%1,%2,%3}, [%4];"
                 : "=r"(r0), "=r"(r1), "=r"(r2), "=r"(r3) : "r"(addr));
}
__device__ __forceinline__ void mma_bf16(float* c,
                                         uint32_t a0, uint32_t a1, uint32_t a2, uint32_t a3,
                                         uint32_t b0, uint32_t b1) {
    asm volatile("mma.sync.aligned.m16n8k16.row.col.f32.bf16.bf16.f32 "
                 "{%0,%1,%2,%3}, {%4,%5,%6,%7}, {%8,%9}, {%0,%1,%2,%3};"
                 : "+f"(c[0]), "+f"(c[1]), "+f"(c[2]), "+f"(c[3])
                 : "r"(a0), "r"(a1), "r"(a2), "r"(a3), "r"(b0), "r"(b1));
}
__device__ __forceinline__ __nv_bfloat16 f2bf(float x) { return __float2bfloat16_rn(x); }

#define CP16(dst, src) \
    asm volatile("cp.async.cg.shared.global [%0], [%1], 16;" :: "r"(dst), "l"(src) : "memory")
#define CP_COMMIT()  asm volatile("cp.async.commit_group;" ::: "memory")
#define CP_WAIT1()   asm volatile("cp.async.wait_group 1;" ::: "memory")

// ===================== bf16 mma.sync GEMM (round-5 validated config) ==========
// C[M, N] = A[M, 768](bf16) * W[N, 768](bf16)^T, fp32 accumulate.
// tile 128x128, BK=32, 3-stage cp.async pipeline (dynamic smem). 8 warps, 64x32 each.
// mode 0: write bf16 to outBF (no act).
// mode 1: fused epilogue: cols <768 -> w = v + bias; dt = softplus(w), p = 1/(1+e^w)
//         packed as bf16x2 into outDP; cols 768..783 -> Bm; 784..799 -> Cm; >=800 off.
#define GK 768
#define CHKB 32
#define NKB (GK / CHKB)                 // 24
#define SRB 40                          // 32 + 8 pad bf16 (80B row; LDSM conflict-free)
#define ROWB (SRB * 2)                  // 80 bytes per smem row
#define MATB (128 * ROWB)               // 10240 bytes per matrix per stage
#define STGB (2 * MATB)                 // 20480 bytes per stage (A + W)
#define GEMM_SMEM (3 * STGB)            // 61440

__global__ __launch_bounds__(256, 2)
void gemm_bf16(const __nv_bfloat16* __restrict__ A, const __nv_bfloat16* __restrict__ W,
               const float* __restrict__ bias, __nv_bfloat16* __restrict__ outBF,
               uint32_t* __restrict__ outDP,
               __nv_bfloat16* __restrict__ Bm, __nv_bfloat16* __restrict__ Cm, int mode)
{
    extern __shared__ __align__(16) char smem_raw[];
    const uint32_t sbase = smem_u32(smem_raw);

    const int tid  = threadIdx.x;
    const int wid  = tid >> 5;
    const int lane = tid & 31;
    const int bn   = blockIdx.x * 128;
    const int bm   = blockIdx.y * 128;
    const int wm   = (wid & 1) * 64;
    const int wn   = (wid >> 1) * 32;

    float acc[4][4][4];
    #pragma unroll
    for (int i = 0; i < 4; i++)
        #pragma unroll
        for (int j = 0; j < 4; j++)
            #pragma unroll
            for (int c = 0; c < 4; c++) acc[i][j][c] = 0.f;

    // cp.async pattern: per chunk per matrix 128 rows x 64B = 512 x 16B; 2/thread/matrix
    const int r0 = tid >> 2;              // 0..63
    const int c8 = (tid & 3) * 8;         // bf16 elem offset 0,8,16,24
    const __nv_bfloat16* Aptr = A + (size_t)(bm + r0) * GK + c8;
    const __nv_bfloat16* Wptr = W + (size_t)(bn + r0) * GK + c8;
    const size_t gstep = (size_t)64 * GK;

    const uint32_t dA0 = sbase + (uint32_t)(r0 * ROWB + c8 * 2);
    const uint32_t dW0 = dA0 + MATB;

    auto issue = [&](int k) {
        uint32_t off = (uint32_t)(k % 3) * STGB;
        const __nv_bfloat16* a0 = Aptr + (size_t)k * CHKB;
        const __nv_bfloat16* w0 = Wptr + (size_t)k * CHKB;
        CP16(dA0 + off,                 a0);
        CP16(dA0 + off + 64u * ROWB,    a0 + gstep);
        CP16(dW0 + off,                 w0);
        CP16(dW0 + off + 64u * ROWB,    w0 + gstep);
        CP_COMMIT();
    };

    // ldmatrix lane addressing (validated round 4)
    const int arow = lane & 15;                       // A: rows m0..15
    const int ak   = (lane >> 4) * 8;                 // A: k half
    const int brow = ((lane >> 4) * 8) + (lane & 7);  // B: n row within 16
    const int bk   = ((lane >> 3) & 1) * 8;           // B: k half

    const uint32_t aAddr0 = sbase + (uint32_t)((wm + arow) * ROWB + ak * 2);
    const uint32_t bAddr0 = sbase + MATB + (uint32_t)((wn + brow) * ROWB + bk * 2);

    issue(0);
    issue(1);

    for (int k = 0; k < NKB; k++) {
        CP_WAIT1();
        __syncthreads();
        if (k + 2 < NKB) issue(k + 2);

        const uint32_t off = (uint32_t)(k % 3) * STGB;
        #pragma unroll
        for (int ks = 0; ks < 2; ks++) {
            const uint32_t koff = off + (uint32_t)(ks * 32);   // 16 bf16 = 32 bytes
            uint32_t bf[4][2];
            ldsm_x4(bAddr0 + koff,               bf[0][0], bf[0][1], bf[1][0], bf[1][1]);
            ldsm_x4(bAddr0 + koff + 16u * ROWB,  bf[2][0], bf[2][1], bf[3][0], bf[3][1]);
            #pragma unroll
            for (int mf = 0; mf < 4; mf++) {
                uint32_t a0, a1, a2, a3;
                ldsm_x4(aAddr0 + koff + (uint32_t)(mf * 16 * ROWB), a0, a1, a2, a3);
                #pragma unroll
                for (int nf = 0; nf < 4; nf++)
                    mma_bf16(acc[mf][nf], a0, a1, a2, a3, bf[nf][0], bf[nf][1]);
            }
        }
    }

    // epilogue: c0/c1 = (row, col/col+1); c2/c3 = row+8
    const int erow = lane >> 2;
    const int ecol = (lane & 3) * 2;
    #pragma unroll
    for (int mf = 0; mf < 4; mf++) {
        int row = bm + wm + mf * 16 + erow;
        #pragma unroll
        for (int nf = 0; nf < 4; nf++) {
            int col = bn + wn + nf * 8 + ecol;
            float v0 = acc[mf][nf][0], v1 = acc[mf][nf][1];
            float v2 = acc[mf][nf][2], v3 = acc[mf][nf][3];
            if (mode == 0) {
                __nv_bfloat162 p0 = { f2bf(v0), f2bf(v1) };
                __nv_bfloat162 p1 = { f2bf(v2), f2bf(v3) };
                *reinterpret_cast<__nv_bfloat162*>(outBF + (size_t)row * D_MODEL + col)       = p0;
                *reinterpret_cast<__nv_bfloat162*>(outBF + (size_t)(row + 8) * D_MODEL + col) = p1;
            } else if (col < 768) {
                float b0 = bias[col], b1 = bias[col + 1];
                float w0 = v0 + b0, w1 = v1 + b1, w2 = v2 + b0, w3 = v3 + b1;
                float e0 = __expf(w0), e1 = __expf(w1), e2 = __expf(w2), e3 = __expf(w3);
                float dt0 = (w0 > 20.f) ? w0 : log1pf(e0);
                float dt1 = (w1 > 20.f) ? w1 : log1pf(e1);
                float dt2 = (w2 > 20.f) ? w2 : log1pf(e2);
                float dt3 = (w3 > 20.f) ? w3 : log1pf(e3);
                float q0 = __fdividef(1.f, 1.f + e0);
                float q1 = __fdividef(1.f, 1.f + e1);
                float q2 = __fdividef(1.f, 1.f + e2);
                float q3 = __fdividef(1.f, 1.f + e3);
                __nv_bfloat162 dp0 = { f2bf(dt0), f2bf(q0) };
                __nv_bfloat162 dp1 = { f2bf(dt1), f2bf(q1) };
                __nv_bfloat162 dp2 = { f2bf(dt2), f2bf(q2) };
                __nv_bfloat162 dp3 = { f2bf(dt3), f2bf(q3) };
                uint2 lo = { *reinterpret_cast<uint32_t*>(&dp0), *reinterpret_cast<uint32_t*>(&dp1) };
                uint2 hi = { *reinterpret_cast<uint32_t*>(&dp2), *reinterpret_cast<uint32_t*>(&dp3) };
                *reinterpret_cast<uint2*>(outDP + (size_t)row * D_MODEL + col)       = lo;
                *reinterpret_cast<uint2*>(outDP + (size_t)(row + 8) * D_MODEL + col) = hi;
            } else if (col < 784) {
                int n = col - 768;
                __nv_bfloat162 p0 = { f2bf(v0), f2bf(v1) };
                __nv_bfloat162 p1 = { f2bf(v2), f2bf(v3) };
                *reinterpret_cast<__nv_bfloat162*>(Bm + (size_t)row * D_STATE + n)       = p0;
                *reinterpret_cast<__nv_bfloat162*>(Bm + (size_t)(row + 8) * D_STATE + n) = p1;
            } else if (col < 800) {
                int n = col - 784;
                __nv_bfloat162 p0 = { f2bf(v0), f2bf(v1) };
                __nv_bfloat162 p1 = { f2bf(v2), f2bf(v3) };
                *reinterpret_cast<__nv_bfloat162*>(Cm + (size_t)row * D_STATE + n)       = p0;
                *reinterpret_cast<__nv_bfloat162*>(Cm + (size_t)(row + 8) * D_STATE + n) = p1;
            }
        }
    }
}

// ---------------- fp32 -> bf16 bulk convert ----------------------------------
__global__ void cvt_f32_bf16(const float* __restrict__ in, __nv_bfloat16* __restrict__ out, int n4)
{
    int idx = blockIdx.x * blockDim.x + threadIdx.x;
    if (idx >= n4) return;
    float4 v = reinterpret_cast<const float4*>(in)[idx];
    __nv_bfloat162 lo = { f2bf(v.x), f2bf(v.y) };
    __nv_bfloat162 hi = { f2bf(v.z), f2bf(v.w) };
    uint2 u = { *reinterpret_cast<uint32_t*>(&lo), *reinterpret_cast<uint32_t*>(&hi) };
    reinterpret_cast<uint2*>(out)[idx] = u;
}

// ---------------- build concatenated weight (bf16) ---------------------------
__global__ void build_wcat(const float* __restrict__ W_dt, const float* __restrict__ W_B,
                           const float* __restrict__ W_C, __nv_bfloat16* __restrict__ out)
{
    int idx = blockIdx.x * blockDim.x + threadIdx.x;
    if (idx >= NCAT * D_MODEL / 4) return;
    int r  = idx / (D_MODEL / 4);
    int c4 = (idx % (D_MODEL / 4)) * 4;
    float4 v = make_float4(0.f, 0.f, 0.f, 0.f);
    if (r < 768)      v = *reinterpret_cast<const float4*>(W_dt + (size_t)r * D_MODEL + c4);
    else if (r < 784) v = *reinterpret_cast<const float4*>(W_B + (size_t)(r - 768) * D_MODEL + c4);
    else if (r < 800) v = *reinterpret_cast<const float4*>(W_C + (size_t)(r - 784) * D_MODEL + c4);
    __nv_bfloat162 lo = { f2bf(v.x), f2bf(v.y) };
    __nv_bfloat162 hi = { f2bf(v.z), f2bf(v.w) };
    uint2 u = { *reinterpret_cast<uint32_t*>(&lo), *reinterpret_cast<uint32_t*>(&hi) };
    reinterpret_cast<uint2*>(out)[idx] = u;
}

// ---------------- depthwise causal conv (K=4) + bias + SiLU, bf16 in/out -----
__global__ void conv_silu_bf16(const __nv_bfloat16* __restrict__ xin,
                               const float* __restrict__ cw,
                               const float* __restrict__ cb,
                               __nv_bfloat16* __restrict__ out)
{
    int idx = blockIdx.x * blockDim.x + threadIdx.x;   // pair index
    if (idx >= M_ROWS * D_MODEL / 2) return;
    int d2 = idx % (D_MODEL / 2);
    int t  = (idx / (D_MODEL / 2)) % T_SEQ;
    int d  = d2 * 2;

    float a0 = cb[d], a1 = cb[d + 1];
    #pragma unroll
    for (int k = 0; k < D_CONV; k++) {
        int rel = k - (D_CONV - 1);
        if (t + rel >= 0) {
            __nv_bfloat162 xv = reinterpret_cast<const __nv_bfloat162*>(xin)[idx + rel * (D_MODEL / 2)];
            float f0 = __bfloat162float(xv.x), f1 = __bfloat162float(xv.y);
            a0 = fmaf(f0, cw[d * D_CONV + k], a0);
            a1 = fmaf(f1, cw[(d + 1) * D_CONV + k], a1);
        }
    }
    float s0 = a0 / (1.f + __expf(-a0));
    float s1 = a1 / (1.f + __expf(-a1));
    __nv_bfloat162 o = { f2bf(s0), f2bf(s1) };
    reinterpret_cast<__nv_bfloat162*>(out)[idx] = o;
}

// ---------------- scan helpers ------------------------------------------------
__device__ __forceinline__ void load_A_and_mode(const float* __restrict__ A_log,
                                                int d, float* A, bool& fast)
{
    #pragma unroll
    for (int n = 0; n < D_STATE; n++) A[n] = -__expf(A_log[d * D_STATE + n]);
    fast = true;
    // fast path requires A[n] = (n+1) * A0 AND A0 == -1 (p = exp(-dt) precomputed)
    fast = fast && (fabsf(A[0] + 1.f) <= 1e-5f);
    #pragma unroll
    for (int n = 1; n < D_STATE; n++)
        fast = fast && (fabsf(A[n] - (float)(n + 1) * A[0]) <= 1e-4f * fabsf(A[n]));
}

// scalar powers: pw[n] = p^(n+1)
__device__ __forceinline__ void powers16(float p1, float* pw)
{
    float p2 = p1 * p1, p4 = p2 * p2, p8 = p4 * p4;
    pw[0] = p1;        pw[1] = p2;        pw[2] = p2 * p1;   pw[3] = p4;
    pw[4] = p4 * p1;   pw[5] = p4 * p2;   pw[6] = p4 * pw[2]; pw[7] = p8;
    pw[8] = p8 * p1;   pw[9] = p8 * p2;   pw[10] = p8 * pw[2]; pw[11] = p8 * p4;
    pw[12] = p8 * pw[4]; pw[13] = p8 * pw[5]; pw[14] = p8 * pw[6]; pw[15] = p8 * p8;
}

// packed bf16x2 powers from bf16 base: pw2[k] = (p^(2k+1), p^(2k+2))
__device__ __forceinline__ void powers16_h2b(__nv_bfloat16 p, __nv_bfloat162* pw2)
{
    __nv_bfloat16 psq = __hmul(p, p);
    __nv_bfloat162 st = { psq, psq };
    pw2[0].x = p; pw2[0].y = psq;
    #pragma unroll
    for (int k = 1; k < 8; k++) pw2[k] = __hmul2(pw2[k - 1], st);
}

#define PFD 8   // prefetch distance (steps) — one full group ahead

// pass 1: per-chunk local scan from h=0; emit end-state and cumulative decay
__global__ __launch_bounds__(256)
void scan_pass1(const uint32_t* __restrict__ dp, const __nv_bfloat16* __restrict__ Bm,
                const __nv_bfloat16* __restrict__ x, const float* __restrict__ A_log,
                float* __restrict__ hend, float* __restrict__ Pp)
{
    __shared__ __align__(16) __nv_bfloat162 sB[TCH * 8];
    int d  = blockIdx.x * blockDim.x + threadIdx.x;
    int ch = blockIdx.y;
    int b  = blockIdx.z;
    int t0 = ch * TCH;

    {
        const uint4* src = reinterpret_cast<const uint4*>(Bm + ((size_t)(b * T_SEQ + t0)) * D_STATE);
        uint4* dst = reinterpret_cast<uint4*>(sB);
        for (int i = threadIdx.x; i < TCH * D_STATE / 8; i += blockDim.x) dst[i] = src[i];
    }
    __syncthreads();

    float A[D_STATE]; bool fast;
    load_A_and_mode(A_log, d, A, fast);

    const uint32_t* dpp     = dp + ((size_t)(b * T_SEQ + t0)) * D_MODEL + d;
    const __nv_bfloat16* xp = x  + ((size_t)(b * T_SEQ + t0)) * D_MODEL + d;
    size_t base = ((size_t)(b * NCH + ch) * D_STATE) * D_MODEL + d;

    if (fast) {
        const float A0 = A[0];
        __nv_bfloat162 h2[8];
        #pragma unroll
        for (int k = 0; k < 8; k++) h2[k] = __floats2bfloat162_rn(0.f, 0.f);
        float S = 0.f;

        uint32_t cur_dp[PFD]; __nv_bfloat16 cur_x[PFD];
        #pragma unroll
        for (int j = 0; j < PFD; j++) {
            cur_dp[j] = dpp[(size_t)j * D_MODEL];
            cur_x[j]  = xp [(size_t)j * D_MODEL];
        }
        for (int t = 0; t < TCH; t += PFD) {
            uint32_t nxt_dp[PFD]; __nv_bfloat16 nxt_x[PFD];
            if (t + PFD < TCH) {
                #pragma unroll
                for (int j = 0; j < PFD; j++) {
                    nxt_dp[j] = dpp[(size_t)(t + PFD + j) * D_MODEL];
                    nxt_x[j]  = xp [(size_t)(t + PFD + j) * D_MODEL];
                }
            }
            #pragma unroll
            for (int j = 0; j < PFD; j++) {
                __nv_bfloat162 dpv = *reinterpret_cast<__nv_bfloat162*>(&cur_dp[j]);
                float dtf = __bfloat162float(dpv.x);
                float u   = __bfloat162float(cur_x[j]) * dtf;
                S += dtf;
                __nv_bfloat162 pw2[8];
                powers16_h2b(dpv.y, pw2);
                __nv_bfloat162 u2 = __float2bfloat162_rn(u);
                const uint4* brow = reinterpret_cast<const uint4*>(sB + (t + j) * 8);
                uint4 br0 = brow[0], br1 = brow[1];
                const __nv_bfloat162* b2a = reinterpret_cast<const __nv_bfloat162*>(&br0);
                const __nv_bfloat162* b2b = reinterpret_cast<const __nv_bfloat162*>(&br1);
                #pragma unroll
                for (int k = 0; k < 4; k++)
                    h2[k] = __hfma2(h2[k], pw2[k], __hmul2(u2, b2a[k]));
                #pragma unroll
                for (int k = 0; k < 4; k++)
                    h2[4 + k] = __hfma2(h2[4 + k], pw2[4 + k], __hmul2(u2, b2b[k]));
            }
            #pragma unroll
            for (int j = 0; j < PFD; j++) { cur_dp[j] = nxt_dp[j]; cur_x[j] = nxt_x[j]; }
        }
        float pw[16];
        powers16(__expf(A0 * S), pw);
        #pragma unroll
        for (int k = 0; k < 8; k++) {
            float2 hf = __bfloat1622float2(h2[k]);
            hend[base + (size_t)(2 * k)     * D_MODEL] = hf.x;
            hend[base + (size_t)(2 * k + 1) * D_MODEL] = hf.y;
            Pp  [base + (size_t)(2 * k)     * D_MODEL] = pw[2 * k];
            Pp  [base + (size_t)(2 * k + 1) * D_MODEL] = pw[2 * k + 1];
        }
    } else {
        float h[D_STATE], P[D_STATE];
        #pragma unroll
        for (int n = 0; n < D_STATE; n++) { h[n] = 0.f; P[n] = 1.f; }
        const __nv_bfloat16* sBs = reinterpret_cast<const __nv_bfloat16*>(sB);
        for (int t = 0; t < TCH; t++) {
            uint32_t dpw = dpp[(size_t)t * D_MODEL];
            __nv_bfloat162 dpv = *reinterpret_cast<__nv_bfloat162*>(&dpw);
            float dtv = __bfloat162float(dpv.x);
            float xv  = __bfloat162float(xp[(size_t)t * D_MODEL]);
            float u   = xv * dtv;
            #pragma unroll
            for (int n = 0; n < D_STATE; n++) {
                float pw = __expf(A[n] * dtv);
                h[n] = fmaf(h[n], pw, u * __bfloat162float(sBs[t * D_STATE + n]));
                P[n] *= pw;
            }
        }
        #pragma unroll
        for (int n = 0; n < D_STATE; n++) {
            hend[base + (size_t)n * D_MODEL] = h[n];
            Pp  [base + (size_t)n * D_MODEL] = P[n];
        }
    }
}

// pass 2: sequential combine over chunks -> chunk-entry states
__global__ void scan_combine(const float* __restrict__ hend, const float* __restrict__ Pp,
                             float* __restrict__ sin_)
{
    int idx = blockIdx.x * blockDim.x + threadIdx.x;
    if (idx >= B_SZ * D_STATE * D_MODEL) return;
    int d = idx % D_MODEL;
    int n = (idx / D_MODEL) % D_STATE;
    int b = idx / (D_MODEL * D_STATE);

    float s = 0.f;
    for (int ch = 0; ch < NCH; ch++) {
        size_t off = ((size_t)(b * NCH + ch) * D_STATE + n) * D_MODEL + d;
        sin_[off] = s;
        s = fmaf(Pp[off], s, hend[off]);
    }
}

// pass 3: replay chunks with correct entry state; emit y + residual
__global__ __launch_bounds__(256)
void scan_pass3(const uint32_t* __restrict__ dp, const __nv_bfloat16* __restrict__ Bm,
                const __nv_bfloat16* __restrict__ Cm, const float* __restrict__ x,
                const float* __restrict__ A_log, const float* __restrict__ Dp,
                const float* __restrict__ sin_, float* __restrict__ y)
{
    __shared__ __align__(16) __nv_bfloat162 sB[TCH * 8];
    __shared__ __align__(16) __nv_bfloat162 sC[TCH * 8];
    int d  = blockIdx.x * blockDim.x + threadIdx.x;
    int ch = blockIdx.y;
    int b  = blockIdx.z;
    int t0 = ch * TCH;

    {
        const uint4* srcB = reinterpret_cast<const uint4*>(Bm + ((size_t)(b * T_SEQ + t0)) * D_STATE);
        const uint4* srcC = reinterpret_cast<const uint4*>(Cm + ((size_t)(b * T_SEQ + t0)) * D_STATE);
        uint4* dB = reinterpret_cast<uint4*>(sB);
        uint4* dC = reinterpret_cast<uint4*>(sC);
        for (int i = threadIdx.x; i < TCH * D_STATE / 8; i += blockDim.x) { dB[i] = srcB[i]; dC[i] = srcC[i]; }
    }
    __syncthreads();

    float A[D_STATE]; bool fast;
    load_A_and_mode(A_log, d, A, fast);

    size_t base = ((size_t)(b * NCH + ch) * D_STATE) * D_MODEL + d;
    float dpar = Dp[d];
    const uint32_t* dpp = dp + ((size_t)(b * T_SEQ + t0)) * D_MODEL + d;
    const float* xp     = x  + ((size_t)(b * T_SEQ + t0)) * D_MODEL + d;
    float* yp           = y  + ((size_t)(b * T_SEQ + t0)) * D_MODEL + d;

    if (fast) {
        __nv_bfloat162 h2[8];
        #pragma unroll
        for (int k = 0; k < 8; k++)
            h2[k] = __floats2bfloat162_rn(sin_[base + (size_t)(2 * k) * D_MODEL],
                                          sin_[base + (size_t)(2 * k + 1) * D_MODEL]);

        uint32_t cur_dp[PFD]; float cur_x[PFD];
        #pragma unroll
        for (int j = 0; j < PFD; j++) {
            cur_dp[j] = dpp[(size_t)j * D_MODEL];
            cur_x[j]  = xp [(size_t)j * D_MODEL];
        }
        for (int t = 0; t < TCH; t += PFD) {
            uint32_t nxt_dp[PFD]; float nxt_x[PFD];
            if (t + PFD < TCH) {
                #pragma unroll
                for (int j = 0; j < PFD; j++) {
                    nxt_dp[j] = dpp[(size_t)(t + PFD + j) * D_MODEL];
                    nxt_x[j]  = xp [(size_t)(t + PFD + j) * D_MODEL];
                }
            }
            float yv[PFD];
            #pragma unroll
            for (int j = 0; j < PFD; j++) {
                __nv_bfloat162 dpv = *reinterpret_cast<__nv_bfloat162*>(&cur_dp[j]);
                float u = cur_x[j] * __bfloat162float(dpv.x);
                __nv_bfloat162 pw2[8];
                powers16_h2b(dpv.y, pw2);
                __nv_bfloat162 u2 = __float2bfloat162_rn(u);
                const uint4* browp = reinterpret_cast<const uint4*>(sB + (t + j) * 8);
                const uint4* crowp = reinterpret_cast<const uint4*>(sC + (t + j) * 8);
                uint4 br0 = browp[0], br1 = browp[1];
                uint4 cr0 = crowp[0], cr1 = crowp[1];
                const __nv_bfloat162* b2a = reinterpret_cast<const __nv_bfloat162*>(&br0);
                const __nv_bfloat162* b2b = reinterpret_cast<const __nv_bfloat162*>(&br1);
                const __nv_bfloat162* c2a = reinterpret_cast<const __nv_bfloat162*>(&cr0);
                const __nv_bfloat162* c2b = reinterpret_cast<const __nv_bfloat162*>(&cr1);
                __nv_bfloat162 acc2 = __floats2bfloat162_rn(0.f, 0.f);
                #pragma unroll
                for (int k = 0; k < 4; k++) {
                    h2[k] = __hfma2(h2[k], pw2[k], __hmul2(u2, b2a[k]));
                    acc2  = __hfma2(h2[k], c2a[k], acc2);
                }
                #pragma unroll
                for (int k = 0; k < 4; k++) {
                    h2[4 + k] = __hfma2(h2[4 + k], pw2[4 + k], __hmul2(u2, b2b[k]));
                    acc2      = __hfma2(h2[4 + k], c2b[k], acc2);
                }
                float2 af = __bfloat1622float2(acc2);
                yv[j] = fmaf(cur_x[j], dpar, af.x + af.y);
            }
            #pragma unroll
            for (int j = 0; j < PFD; j++)
                yp[(size_t)(t + j) * D_MODEL] = yv[j];
            #pragma unroll
            for (int j = 0; j < PFD; j++) { cur_dp[j] = nxt_dp[j]; cur_x[j] = nxt_x[j]; }
        }
    } else {
        float h[D_STATE];
        #pragma unroll
        for (int n = 0; n < D_STATE; n++) h[n] = sin_[base + (size_t)n * D_MODEL];
        const __nv_bfloat16* sBs = reinterpret_cast<const __nv_bfloat16*>(sB);
        const __nv_bfloat16* sCs = reinterpret_cast<const __nv_bfloat16*>(sC);
        for (int t = 0; t < TCH; t++) {
            uint32_t dpw = dpp[(size_t)t * D_MODEL];
            __nv_bfloat162 dpv = *reinterpret_cast<__nv_bfloat162*>(&dpw);
            float dtv = __bfloat162float(dpv.x);
            float xv  = xp [(size_t)t * D_MODEL];
            float u   = xv * dtv;
            float acc = 0.f;
            #pragma unroll
            for (int n = 0; n < D_STATE; n++) {
                float pw = __expf(A[n] * dtv);
                h[n] = fmaf(h[n], pw, u * __bfloat162float(sBs[t * D_STATE + n]));
                acc  = fmaf(h[n], __bfloat162float(sCs[t * D_STATE + n]), acc);
            }
            yp[(size_t)t * D_MODEL] = fmaf(xv, dpar, acc);
        }
    }
}

// ---------------- launch ------------------------------------------------------
extern "C" void kernel_launch(void* const* d_in, const int* in_sizes, int n_in,
                              void* d_out, int out_size)
{
    const float* x      = (const float*)d_in[0];
    const float* W_in   = (const float*)d_in[1];
    const float* conv_w = (const float*)d_in[2];
    const float* conv_b = (const float*)d_in[3];
    const float* W_dt   = (const float*)d_in[4];
    const float* b_dt   = (const float*)d_in[5];
    const float* A_log  = (const float*)d_in[6];
    const float* D_par  = (const float*)d_in[7];
    const float* W_B    = (const float*)d_in[8];
    const float* W_C    = (const float*)d_in[9];
    float* y = (float*)d_out;

    __nv_bfloat16 *xbf, *xssm_bf, *xconv_bf, *win_bf, *wcat_bf, *Bmbf, *Cmbf;
    uint32_t* dpb;
    float *hend, *Pp, *sin_;
    cudaGetSymbolAddress((void**)&xbf,      g_xbf);
    cudaGetSymbolAddress((void**)&xssm_bf,  g_xssm_bf);
    cudaGetSymbolAddress((void**)&xconv_bf, g_xconv_bf);
    cudaGetSymbolAddress((void**)&win_bf,   g_Win_bf);
    cudaGetSymbolAddress((void**)&wcat_bf,  g_Wcat_bf);
    cudaGetSymbolAddress((void**)&dpb,   g_dp);
    cudaGetSymbolAddress((void**)&Bmbf,  g_Bmbf);
    cudaGetSymbolAddress((void**)&Cmbf,  g_Cmbf);
    cudaGetSymbolAddress((void**)&hend,  g_hend);
    cudaGetSymbolAddress((void**)&Pp,    g_Pp);
    cudaGetSymbolAddress((void**)&sin_,  g_sin);

    cudaFuncSetAttribute(gemm_bf16, cudaFuncAttributeMaxDynamicSharedMemorySize, GEMM_SMEM);

    // 0) precision prep: x -> bf16; W_in[:768] -> bf16; [W_dt; W_B; W_C; 0] -> bf16
    int n4x = M_ROWS * D_MODEL / 4;
    cvt_f32_bf16<<<(n4x + 255) / 256, 256>>>(x, xbf, n4x);
    int n4w = D_MODEL * D_MODEL / 4;
    cvt_f32_bf16<<<(n4w + 255) / 256, 256>>>(W_in, win_bf, n4w);
    int n4c = NCAT * D_MODEL / 4;
    build_wcat<<<(n4c + 255) / 256, 256>>>(W_dt, W_B, W_C, wcat_bf);

    // 1) x_ssm = x @ W_in[:768].T  (z half is dead code); bf16 out
    dim3 g1(D_MODEL / 128, M_ROWS / 128);
    gemm_bf16<<<g1, 256, GEMM_SMEM>>>(xbf, win_bf, nullptr, xssm_bf,
                                      nullptr, nullptr, nullptr, 0);

    // 2) depthwise causal conv + bias + SiLU (bf16 -> bf16)
    int pairs = M_ROWS * D_MODEL / 2;
    conv_silu_bf16<<<(pairs + 255) / 256, 256>>>(xssm_bf, conv_w, conv_b, xconv_bf);

    // 3) fused: packed (dt, p = exp(-dt)) bf16x2; Bm/Cm (bf16)
    dim3 g2(NCAT / 128, M_ROWS / 128);
    gemm_bf16<<<g2, 256, GEMM_SMEM>>>(xconv_bf, wcat_bf, b_dt, nullptr,
                                      dpb, Bmbf, Cmbf, 1);

    // 4-6) chunked associative scan (32 chunks; 8-step prefetch depth)
    dim3 scan_grid(D_MODEL / 256, NCH, B_SZ);
    scan_pass1<<<scan_grid, 256>>>(dpb, Bmbf, xbf, A_log, hend, Pp);
    scan_combine<<<(B_SZ * D_STATE * D_MODEL + 255) / 256, 256>>>(hend, Pp, sin_);
    scan_pass3<<<scan_grid, 256>>>(dpb, Bmbf, Cmbf, x, A_log, D_par, sin_, y);
}